// round 2
// baseline (speedup 1.0000x reference)
#include <cuda_runtime.h>
#include <math.h>
#include <stdint.h>

#define BB 16
#define QQ 1024
#define TT 1024
#define DD 256
#define EPS 0.1f
#define INV_EPS 10.0f
#define N_ITERS 5

// ---------------- device scratch (no allocations allowed) ----------------
__device__ float g_cost[(size_t)BB * QQ * TT];  // 64 MB cost matrix
__device__ float g_u[BB * QQ];
__device__ float g_v[BB * TT];
__device__ float g_x2[BB * QQ];
__device__ float g_y2[BB * TT];
__device__ unsigned int g_maxbits;              // global max(cost) as ordered uint

// ---------------- init ----------------
__global__ void init_kernel() {
    int i = blockIdx.x * blockDim.x + threadIdx.x;
    if (i == 0) g_maxbits = 0u;
    if (i < BB * QQ) g_u[i] = 0.0f;
    if (i < BB * TT) g_v[i] = 0.0f;
}

// ---------------- squared row norms: one warp per row ----------------
__global__ void norms_kernel(const float* __restrict__ preds,
                             const float* __restrict__ tgts) {
    int gwarp = (blockIdx.x * blockDim.x + threadIdx.x) >> 5;
    int lane = threadIdx.x & 31;
    const int NROWS = BB * QQ + BB * TT;
    if (gwarp >= NROWS) return;
    const float* src = (gwarp < BB * QQ)
                           ? preds + (size_t)gwarp * DD
                           : tgts + (size_t)(gwarp - BB * QQ) * DD;
    float s = 0.0f;
#pragma unroll
    for (int k = lane; k < DD; k += 32) {
        float x = src[k];
        s = fmaf(x, x, s);
    }
#pragma unroll
    for (int o = 16; o > 0; o >>= 1) s += __shfl_xor_sync(0xffffffffu, s, o);
    if (lane == 0) {
        if (gwarp < BB * QQ) g_x2[gwarp] = s;
        else g_y2[gwarp - BB * QQ] = s;
    }
}

// ---------------- cost = sqrt(max(x2+y2-2*A.B^T, 0)); track global max ----
// 128x128 tile, BK=8, 256 threads, 8x8 microtile per thread.
// Inner product via packed fp32x2 FMA (fma.rn.f32x2) -> 2x fp32 throughput.
__global__ void __launch_bounds__(256, 2)
cost_kernel(const float* __restrict__ preds, const float* __restrict__ tgts) {
    const int b = blockIdx.z;
    const int m_base = blockIdx.y * 128;
    const int n_base = blockIdx.x * 128;
    const float* Ag = preds + ((size_t)b * QQ + m_base) * DD;
    const float* Bg = tgts + ((size_t)b * TT + n_base) * DD;

    __shared__ float As[8][128];
    __shared__ float Bs[8][128];

    const int tid = threadIdx.x;
    const int lrow = tid >> 1;          // 0..127
    const int lcol = (tid & 1) << 2;    // 0 or 4
    const int tx = tid & 15;            // n microtile
    const int ty = tid >> 4;            // m microtile

    // acc[i][jp]: packed pair of fp32 accumulators for columns (2*jp, 2*jp+1)
    unsigned long long acc[8][4] = {};

    for (int k0 = 0; k0 < DD; k0 += 8) {
        float4 av = *(const float4*)(Ag + (size_t)lrow * DD + k0 + lcol);
        float4 bv = *(const float4*)(Bg + (size_t)lrow * DD + k0 + lcol);
        As[lcol + 0][lrow] = av.x;
        As[lcol + 1][lrow] = av.y;
        As[lcol + 2][lrow] = av.z;
        As[lcol + 3][lrow] = av.w;
        Bs[lcol + 0][lrow] = bv.x;
        Bs[lcol + 1][lrow] = bv.y;
        Bs[lcol + 2][lrow] = bv.z;
        Bs[lcol + 3][lrow] = bv.w;
        __syncthreads();
#pragma unroll
        for (int kk = 0; kk < 8; kk++) {
            float ar[8];
            *(float4*)(&ar[0]) = *(const float4*)(&As[kk][ty * 8]);
            *(float4*)(&ar[4]) = *(const float4*)(&As[kk][ty * 8 + 4]);
            // B pairs load directly as packed 64-bit lanes (adjacent floats)
            ulonglong2 bq0 = *(const ulonglong2*)(&Bs[kk][tx * 8]);
            ulonglong2 bq1 = *(const ulonglong2*)(&Bs[kk][tx * 8 + 4]);
            unsigned long long bp0 = bq0.x, bp1 = bq0.y, bp2 = bq1.x, bp3 = bq1.y;
#pragma unroll
            for (int i = 0; i < 8; i++) {
                unsigned long long ai;
                asm("mov.b64 %0, {%1, %1};" : "=l"(ai) : "f"(ar[i]));
                asm("fma.rn.f32x2 %0, %1, %2, %0;" : "+l"(acc[i][0]) : "l"(ai), "l"(bp0));
                asm("fma.rn.f32x2 %0, %1, %2, %0;" : "+l"(acc[i][1]) : "l"(ai), "l"(bp1));
                asm("fma.rn.f32x2 %0, %1, %2, %0;" : "+l"(acc[i][2]) : "l"(ai), "l"(bp2));
                asm("fma.rn.f32x2 %0, %1, %2, %0;" : "+l"(acc[i][3]) : "l"(ai), "l"(bp3));
            }
        }
        __syncthreads();
    }

    // epilogue: cost + max tracking + store
    float tmax = 0.0f;
#pragma unroll
    for (int i = 0; i < 8; i++) {
        float xi = g_x2[b * QQ + m_base + ty * 8 + i];
        float cbuf[8];
#pragma unroll
        for (int jp = 0; jp < 4; jp++) {
            float plo, phi;
            asm("mov.b64 {%0, %1}, %2;" : "=f"(plo), "=f"(phi) : "l"(acc[i][jp]));
            float yj0 = g_y2[b * TT + n_base + tx * 8 + jp * 2];
            float yj1 = g_y2[b * TT + n_base + tx * 8 + jp * 2 + 1];
            float c0 = sqrtf(fmaxf(xi + yj0 - 2.0f * plo, 0.0f));
            float c1 = sqrtf(fmaxf(xi + yj1 - 2.0f * phi, 0.0f));
            cbuf[jp * 2] = c0;
            cbuf[jp * 2 + 1] = c1;
            tmax = fmaxf(tmax, fmaxf(c0, c1));
        }
        size_t off = ((size_t)(b * QQ + m_base + ty * 8 + i)) * TT + n_base + tx * 8;
        *(float4*)(g_cost + off) = make_float4(cbuf[0], cbuf[1], cbuf[2], cbuf[3]);
        *(float4*)(g_cost + off + 4) = make_float4(cbuf[4], cbuf[5], cbuf[6], cbuf[7]);
    }

    __shared__ unsigned int smax;
    if (tid == 0) smax = 0u;
    __syncthreads();
    atomicMax(&smax, __float_as_uint(tmax));  // costs >= 0: uint order == float order
    __syncthreads();
    if (tid == 0) atomicMax(&g_maxbits, smax);
}

// ---------------- block reduction helpers (deterministic) ----------------
__device__ __forceinline__ float block_reduce_max(float v, float* sh8) {
#pragma unroll
    for (int o = 16; o > 0; o >>= 1) v = fmaxf(v, __shfl_xor_sync(0xffffffffu, v, o));
    int w = threadIdx.x >> 5;
    if ((threadIdx.x & 31) == 0) sh8[w] = v;
    __syncthreads();
    float r = sh8[0];
#pragma unroll
    for (int i = 1; i < 8; i++) r = fmaxf(r, sh8[i]);
    __syncthreads();
    return r;
}

__device__ __forceinline__ float block_reduce_sum(float v, float* sh8) {
#pragma unroll
    for (int o = 16; o > 0; o >>= 1) v += __shfl_xor_sync(0xffffffffu, v, o);
    int w = threadIdx.x >> 5;
    if ((threadIdx.x & 31) == 0) sh8[w] = v;
    __syncthreads();
    float r = sh8[0];
#pragma unroll
    for (int i = 1; i < 8; i++) r += sh8[i];
    __syncthreads();
    return r;
}

// ---------------- u update: one block per (b,q) row; float4 loads ----------
__global__ void u_update(const float* __restrict__ filt) {
    const int row = blockIdx.x;       // b*QQ + q
    const int b = row >> 10;
    const float* crow = g_cost + (size_t)row * TT;
    const float* vb = g_v + b * TT;
    const float* fb = filt + b * TT;
    const float fc = 2.0f * __uint_as_float(g_maxbits);
    const int tid = threadIdx.x;
    const int t0 = tid * 4;

    __shared__ float sh8[8];

    float4 c = *(const float4*)(crow + t0);
    float4 f = *(const float4*)(fb + t0);
    float4 v = *(const float4*)(vb + t0);

    float a[4];
    a[0] = (v.x - ((f.x <= 0.0f) ? fc : c.x)) * INV_EPS;
    a[1] = (v.y - ((f.y <= 0.0f) ? fc : c.y)) * INV_EPS;
    a[2] = (v.z - ((f.z <= 0.0f) ? fc : c.z)) * INV_EPS;
    a[3] = (v.w - ((f.w <= 0.0f) ? fc : c.w)) * INV_EPS;

    float m = fmaxf(fmaxf(a[0], a[1]), fmaxf(a[2], a[3]));
    m = block_reduce_max(m, sh8);
    float s = __expf(a[0] - m) + __expf(a[1] - m) + __expf(a[2] - m) + __expf(a[3] - m);
    s = block_reduce_sum(s, sh8);
    if (tid == 0) g_u[row] = -EPS * (__logf(s) + m);
}

// ---------------- v update: block (32,8), lane -> 2 consecutive t ---------
// grid (TT/64, BB). Each thread: online logsumexp over 128 q's (4 in flight).
__global__ void v_update(const float* __restrict__ filt) {
    const int b = blockIdx.y;
    const int lane = threadIdx.x;
    const int wy = threadIdx.y;                 // 0..7
    const int t = blockIdx.x * 64 + lane * 2;
    const float fc = 2.0f * __uint_as_float(g_maxbits);
    float2 fv = *(const float2*)(filt + b * TT + t);
    const bool f0 = (fv.x <= 0.0f), f1 = (fv.y <= 0.0f);
    const float* base = g_cost + ((size_t)b * QQ) * TT + t;
    const float* ub = g_u + b * QQ;

    float m0 = -INFINITY, m1 = -INFINITY, s0 = 0.0f, s1 = 0.0f;
    for (int q0 = wy * 4; q0 < QQ; q0 += 32) {
        float2 c0 = *(const float2*)(base + (size_t)(q0 + 0) * TT);
        float2 c1 = *(const float2*)(base + (size_t)(q0 + 1) * TT);
        float2 c2 = *(const float2*)(base + (size_t)(q0 + 2) * TT);
        float2 c3 = *(const float2*)(base + (size_t)(q0 + 3) * TT);
        float u0 = ub[q0 + 0], u1 = ub[q0 + 1], u2 = ub[q0 + 2], u3 = ub[q0 + 3];
        float2 cc[4] = {c0, c1, c2, c3};
        float uu[4] = {u0, u1, u2, u3};
#pragma unroll
        for (int k = 0; k < 4; k++) {
            float ax = (uu[k] - (f0 ? fc : cc[k].x)) * INV_EPS;
            float ay = (uu[k] - (f1 ? fc : cc[k].y)) * INV_EPS;
            if (ax > m0) { s0 = s0 * __expf(m0 - ax) + 1.0f; m0 = ax; }
            else         { s0 += __expf(ax - m0); }
            if (ay > m1) { s1 = s1 * __expf(m1 - ay) + 1.0f; m1 = ay; }
            else         { s1 += __expf(ay - m1); }
        }
    }

    __shared__ float sm[8][64];
    __shared__ float ss[8][64];
    sm[wy][lane * 2] = m0;
    sm[wy][lane * 2 + 1] = m1;
    ss[wy][lane * 2] = s0;
    ss[wy][lane * 2 + 1] = s1;
    __syncthreads();
    if (wy == 0) {
        float M0 = m0, S0 = s0, M1 = m1, S1 = s1;
#pragma unroll
        for (int w = 1; w < 8; w++) {
            float m2 = sm[w][lane * 2], s2 = ss[w][lane * 2];
            if (m2 > M0) { S0 = S0 * __expf(M0 - m2) + s2; M0 = m2; }
            else         { S0 += s2 * __expf(m2 - M0); }
            float m3 = sm[w][lane * 2 + 1], s3 = ss[w][lane * 2 + 1];
            if (m3 > M1) { S1 = S1 * __expf(M1 - m3) + s3; M1 = m3; }
            else         { S1 += s3 * __expf(m3 - M1); }
        }
        float2 out;
        out.x = -EPS * (__logf(S0) + M0);
        out.y = -EPS * (__logf(S1) + M1);
        *(float2*)(g_v + b * TT + t) = out;
    }
}

// ---------------- final: P = exp((u+v-c)/eps), argmax_t (first max) ------
__global__ void p_argmax_kernel(const float* __restrict__ filt,
                                float* __restrict__ outP,
                                float* __restrict__ outIdx) {
    const int row = blockIdx.x;       // b*QQ + q
    const int b = row >> 10;
    const float* crow = g_cost + (size_t)row * TT;
    const float* vb = g_v + b * TT;
    const float* fb = filt + b * TT;
    const float fc = 2.0f * __uint_as_float(g_maxbits);
    const float u = g_u[row];
    const int tid = threadIdx.x;
    const int t0 = tid * 4;

    float4 c = *(const float4*)(crow + t0);
    float4 f = *(const float4*)(fb + t0);
    float4 v = *(const float4*)(vb + t0);

    float4 p;
    p.x = __expf((u + v.x - ((f.x <= 0.0f) ? fc : c.x)) * INV_EPS);
    p.y = __expf((u + v.y - ((f.y <= 0.0f) ? fc : c.y)) * INV_EPS);
    p.z = __expf((u + v.z - ((f.z <= 0.0f) ? fc : c.z)) * INV_EPS);
    p.w = __expf((u + v.w - ((f.w <= 0.0f) ? fc : c.w)) * INV_EPS);
    if (outP) *(float4*)(outP + (size_t)row * TT + t0) = p;

    float bestv = p.x;
    int besti = t0;
    if (p.y > bestv) { bestv = p.y; besti = t0 + 1; }
    if (p.z > bestv) { bestv = p.z; besti = t0 + 2; }
    if (p.w > bestv) { bestv = p.w; besti = t0 + 3; }

    __shared__ float sv[256];
    __shared__ int si[256];
    sv[tid] = bestv;
    si[tid] = besti;
    __syncthreads();
#pragma unroll
    for (int st = 128; st > 0; st >>= 1) {
        if (tid < st) {
            float v2 = sv[tid + st];
            int i2 = si[tid + st];
            if (v2 > sv[tid] || (v2 == sv[tid] && i2 < si[tid])) {
                sv[tid] = v2;
                si[tid] = i2;
            }
        }
        __syncthreads();
    }
    if (tid == 0 && outIdx) outIdx[row] = (float)si[0];
}

// ---------------- launch ----------------
extern "C" void kernel_launch(void* const* d_in, const int* in_sizes, int n_in,
                              void* d_out, int out_size) {
    const float* preds = (const float*)d_in[0];
    const float* tgts = (const float*)d_in[1];
    const float* filt = (const float*)d_in[2];
    float* out = (float*)d_out;

    const int NP = BB * QQ * TT;
    const int NI = BB * QQ;
    float* outIdx = nullptr;
    float* outP = nullptr;
    if (out_size == NP + NI) { outIdx = out; outP = out + NI; }
    else if (out_size == NP) { outP = out; }
    else if (out_size == NI) { outIdx = out; }
    else { outIdx = out; outP = out + NI; }  // best guess

    init_kernel<<<(BB * QQ + 255) / 256, 256>>>();
    {
        const int nwarps = BB * QQ + BB * TT;  // 32768 rows, one warp each
        norms_kernel<<<(nwarps * 32 + 255) / 256, 256>>>(preds, tgts);
    }
    cost_kernel<<<dim3(TT / 128, QQ / 128, BB), 256>>>(preds, tgts);
    for (int it = 0; it < N_ITERS; it++) {
        u_update<<<BB * QQ, 256>>>(filt);
        v_update<<<dim3(TT / 64, BB), dim3(32, 8)>>>(filt);
    }
    p_argmax_kernel<<<BB * QQ, 256>>>(filt, outP, outIdx);
}

// round 4
// speedup vs baseline: 1.2694x; 1.2694x over previous
#include <cuda_runtime.h>
#include <cuda_bf16.h>
#include <math.h>
#include <stdint.h>

#define BB 16
#define QQ 1024
#define TT 1024
#define DD 256
#define EPS 0.1f
#define INV_EPS 10.0f
#define N_ITERS 5

#define K3 768    // 3*DD bf16 passes: A=[hi,lo,hi], B=[hi,hi,lo]
#define KC 64     // K per stage (64 bf16 = 128B row)
#define STAGES 12 // K3/KC

// ---------------- device scratch (no allocations allowed) ----------------
__device__ float g_cost[(size_t)BB * QQ * TT];        // 64 MB cost matrix
__device__ __nv_bfloat16 g_A3[(size_t)BB * QQ * K3];  // 24 MB split preds
__device__ __nv_bfloat16 g_B3[(size_t)BB * TT * K3];  // 24 MB split targets
__device__ float g_u[BB * QQ];
__device__ float g_v[BB * TT];
__device__ float g_x2[BB * QQ];
__device__ float g_y2[BB * TT];
__device__ unsigned int g_maxbits;

// ---------------- PTX helpers (all baseline sm_80+, compile at compute_103) --
__device__ __forceinline__ uint32_t smem_to_u32(const void* p) {
    uint32_t a;
    asm("{ .reg .u64 t; cvta.to.shared.u64 t, %1; cvt.u32.u64 %0, t; }"
        : "=r"(a) : "l"(p));
    return a;
}
#define CP_ASYNC16(dst, src) \
    asm volatile("cp.async.cg.shared.global [%0], [%1], 16;" :: "r"(dst), "l"(src))
#define CP_COMMIT() asm volatile("cp.async.commit_group;")
#define CP_WAIT1() asm volatile("cp.async.wait_group 1;")
#define CP_WAIT0() asm volatile("cp.async.wait_group 0;")

__device__ __forceinline__ void ldsm_x4(uint32_t& r0, uint32_t& r1, uint32_t& r2,
                                        uint32_t& r3, uint32_t addr) {
    asm volatile("ldmatrix.sync.aligned.m8n8.x4.shared.b16 {%0,%1,%2,%3}, [%4];"
                 : "=r"(r0), "=r"(r1), "=r"(r2), "=r"(r3) : "r"(addr));
}
__device__ __forceinline__ void mma16816(float* d, const uint32_t* a, const uint32_t* b) {
    asm volatile(
        "mma.sync.aligned.m16n8k16.row.col.f32.bf16.bf16.f32 "
        "{%0,%1,%2,%3}, {%4,%5,%6,%7}, {%8,%9}, {%0,%1,%2,%3};"
        : "+f"(d[0]), "+f"(d[1]), "+f"(d[2]), "+f"(d[3])
        : "r"(a[0]), "r"(a[1]), "r"(a[2]), "r"(a[3]), "r"(b[0]), "r"(b[1]));
}

// ---------------- init ----------------
__global__ void init_kernel() {
    int i = blockIdx.x * blockDim.x + threadIdx.x;
    if (i == 0) g_maxbits = 0u;
    if (i < BB * QQ) g_u[i] = 0.0f;
    if (i < BB * TT) g_v[i] = 0.0f;
}

// ------- split fp32 -> bf16 hi/lo (3-pass layout) + row norms; warp/row -----
__global__ void split_norms_kernel(const float* __restrict__ preds,
                                   const float* __restrict__ tgts) {
    int gw = (blockIdx.x * blockDim.x + threadIdx.x) >> 5;
    int lane = threadIdx.x & 31;
    if (gw >= 2 * BB * QQ) return;
    bool isA = gw < BB * QQ;
    int r = isA ? gw : gw - BB * QQ;
    const float* src = (isA ? preds : tgts) + (size_t)r * DD;
    __nv_bfloat16* dst = (isA ? g_A3 : g_B3) + (size_t)r * K3;

    float s = 0.0f;
#pragma unroll
    for (int i = 0; i < 2; i++) {
        int k = lane * 8 + i * 4;
        float4 x = *(const float4*)(src + k);
        s = fmaf(x.x, x.x, s);
        s = fmaf(x.y, x.y, s);
        s = fmaf(x.z, x.z, s);
        s = fmaf(x.w, x.w, s);
        __nv_bfloat16 hx = __float2bfloat16_rn(x.x);
        __nv_bfloat16 hy = __float2bfloat16_rn(x.y);
        __nv_bfloat16 hz = __float2bfloat16_rn(x.z);
        __nv_bfloat16 hw = __float2bfloat16_rn(x.w);
        __nv_bfloat16 lx = __float2bfloat16_rn(x.x - __bfloat162float(hx));
        __nv_bfloat16 ly = __float2bfloat16_rn(x.y - __bfloat162float(hy));
        __nv_bfloat16 lz = __float2bfloat16_rn(x.z - __bfloat162float(hz));
        __nv_bfloat16 lw = __float2bfloat16_rn(x.w - __bfloat162float(hw));
        __nv_bfloat162 h01{hx, hy}, h23{hz, hw}, l01{lx, ly}, l23{lz, lw};
        *(__nv_bfloat162*)(dst + 0 * DD + k) = h01;
        *(__nv_bfloat162*)(dst + 0 * DD + k + 2) = h23;
        *(__nv_bfloat162*)(dst + 1 * DD + k) = isA ? l01 : h01;
        *(__nv_bfloat162*)(dst + 1 * DD + k + 2) = isA ? l23 : h23;
        *(__nv_bfloat162*)(dst + 2 * DD + k) = isA ? h01 : l01;
        *(__nv_bfloat162*)(dst + 2 * DD + k + 2) = isA ? h23 : l23;
    }
#pragma unroll
    for (int o = 16; o > 0; o >>= 1) s += __shfl_xor_sync(0xffffffffu, s, o);
    if (lane == 0) {
        if (isA) g_x2[r] = s;
        else g_y2[r] = s;
    }
}

// --------- cost via mma.sync bf16-split GEMM: CTA = 128x128 tile ------------
// smem: A buf0 @0 (16KB), B buf0 @16K, A buf1 @32K, B buf1 @48K  -> 64KB
#define SM_TOTAL 65536
__global__ void __launch_bounds__(256)
cost_mma_kernel() {
    extern __shared__ char smem[];
    const uint32_t sb = smem_to_u32(smem);
    const int b = blockIdx.z;
    const int m_base = blockIdx.y * 128;
    const int n_base = blockIdx.x * 128;
    const int tid = threadIdx.x;
    const int wid = tid >> 5;
    const int lane = tid & 31;
    const int warp_m = wid >> 2;   // 0..1 -> 64 rows each
    const int warp_n = wid & 3;    // 0..3 -> 32 cols each

    const __nv_bfloat16* Ag = g_A3 + (size_t)(b * QQ + m_base) * K3;
    const __nv_bfloat16* Bg = g_B3 + (size_t)(b * TT + n_base) * K3;

    // cp.async tile loader: 128 rows x 64 bf16 (=8 chunks of 16B), swizzled
    const int ld_r = tid >> 1;                 // base row pattern helper
    (void)ld_r;

    auto load_stage = [&](int s, int buf) {
        uint32_t abase = sb + (uint32_t)buf * 32768u;
        uint32_t bbase = abase + 16384u;
#pragma unroll
        for (int v = 0; v < 4; v++) {
            int idx = tid + v * 256;           // 0..1023
            int r = idx >> 3;
            int g = idx & 7;
            uint32_t off = (uint32_t)(r * 128 + ((g ^ (r & 7)) << 4));
            const __nv_bfloat16* srcA = Ag + (size_t)r * K3 + s * KC + g * 8;
            const __nv_bfloat16* srcB = Bg + (size_t)r * K3 + s * KC + g * 8;
            CP_ASYNC16(abase + off, srcA);
            CP_ASYNC16(bbase + off, srcB);
        }
    };

    // ldmatrix per-lane row geometry
    const int laneA_r = (lane & 7) + ((lane >> 3) & 1) * 8;  // 0..15
    const int khA = (lane >> 4) & 1;
    const int laneB_r = (lane & 7) + ((lane >> 4) & 1) * 8;  // 0..15
    const int khB = (lane >> 3) & 1;
    const int xorA = laneA_r & 7;
    const int xorB = laneB_r & 7;

    float acc[4][4][4];
#pragma unroll
    for (int i = 0; i < 4; i++)
#pragma unroll
        for (int j = 0; j < 4; j++)
#pragma unroll
            for (int e = 0; e < 4; e++) acc[i][j][e] = 0.0f;

    load_stage(0, 0);
    CP_COMMIT();

    for (int s = 0; s < STAGES; s++) {
        const int buf = s & 1;
        if (s + 1 < STAGES) {
            load_stage(s + 1, buf ^ 1);
            CP_COMMIT();
            CP_WAIT1();
        } else {
            CP_WAIT0();
        }
        __syncthreads();

        uint32_t abase = sb + (uint32_t)buf * 32768u;
        uint32_t bbase = abase + 16384u;
#pragma unroll
        for (int kq = 0; kq < 4; kq++) {
            uint32_t afrag[4][4];
            uint32_t bfrag[4][2];
#pragma unroll
            for (int im = 0; im < 4; im++) {
                int row = warp_m * 64 + im * 16 + laneA_r;
                uint32_t addr = abase + (uint32_t)(row * 128 + (((khA + 2 * kq) ^ xorA) << 4));
                ldsm_x4(afrag[im][0], afrag[im][1], afrag[im][2], afrag[im][3], addr);
            }
#pragma unroll
            for (int ip = 0; ip < 2; ip++) {   // each x4 covers 2 n-atoms
                int row = warp_n * 32 + ip * 16 + laneB_r;
                uint32_t addr = bbase + (uint32_t)(row * 128 + (((khB + 2 * kq) ^ xorB) << 4));
                ldsm_x4(bfrag[ip * 2][0], bfrag[ip * 2][1],
                        bfrag[ip * 2 + 1][0], bfrag[ip * 2 + 1][1], addr);
            }
#pragma unroll
            for (int im = 0; im < 4; im++)
#pragma unroll
                for (int in = 0; in < 4; in++)
                    mma16816(acc[im][in], afrag[im], bfrag[in]);
        }
        __syncthreads();
    }

    // epilogue: cost = sqrt(max(x2 + y2 - 2*acc, 0)); float2 stores; track max
    const float* x2p = g_x2 + b * QQ + m_base;
    const float* y2p = g_y2 + b * TT + n_base;
    float tmax = 0.0f;
#pragma unroll
    for (int im = 0; im < 4; im++) {
        int m0 = warp_m * 64 + im * 16 + (lane >> 2);
        float xi0 = x2p[m0];
        float xi1 = x2p[m0 + 8];
#pragma unroll
        for (int in = 0; in < 4; in++) {
            int n0 = warp_n * 32 + in * 8 + (lane & 3) * 2;
            float y0 = y2p[n0];
            float y1 = y2p[n0 + 1];
            float c00 = sqrtf(fmaxf(fmaf(-2.0f, acc[im][in][0], xi0 + y0), 0.0f));
            float c01 = sqrtf(fmaxf(fmaf(-2.0f, acc[im][in][1], xi0 + y1), 0.0f));
            float c10 = sqrtf(fmaxf(fmaf(-2.0f, acc[im][in][2], xi1 + y0), 0.0f));
            float c11 = sqrtf(fmaxf(fmaf(-2.0f, acc[im][in][3], xi1 + y1), 0.0f));
            tmax = fmaxf(tmax, fmaxf(fmaxf(c00, c01), fmaxf(c10, c11)));
            size_t g0 = ((size_t)(b * QQ + m_base + m0)) * TT + n_base + n0;
            size_t g1 = ((size_t)(b * QQ + m_base + m0 + 8)) * TT + n_base + n0;
            *(float2*)(g_cost + g0) = make_float2(c00, c01);
            *(float2*)(g_cost + g1) = make_float2(c10, c11);
        }
    }

    __shared__ unsigned int smax;
    if (tid == 0) smax = 0u;
    __syncthreads();
#pragma unroll
    for (int o = 16; o > 0; o >>= 1)
        tmax = fmaxf(tmax, __shfl_xor_sync(0xffffffffu, tmax, o));
    if (lane == 0) atomicMax(&smax, __float_as_uint(tmax));
    __syncthreads();
    if (tid == 0) atomicMax(&g_maxbits, smax);
}

// ---------------- block reduction helpers ----------------
__device__ __forceinline__ float block_reduce_max(float v, float* sh8) {
#pragma unroll
    for (int o = 16; o > 0; o >>= 1) v = fmaxf(v, __shfl_xor_sync(0xffffffffu, v, o));
    int w = threadIdx.x >> 5;
    if ((threadIdx.x & 31) == 0) sh8[w] = v;
    __syncthreads();
    float r = sh8[0];
#pragma unroll
    for (int i = 1; i < 8; i++) r = fmaxf(r, sh8[i]);
    __syncthreads();
    return r;
}
__device__ __forceinline__ float block_reduce_sum(float v, float* sh8) {
#pragma unroll
    for (int o = 16; o > 0; o >>= 1) v += __shfl_xor_sync(0xffffffffu, v, o);
    int w = threadIdx.x >> 5;
    if ((threadIdx.x & 31) == 0) sh8[w] = v;
    __syncthreads();
    float r = sh8[0];
#pragma unroll
    for (int i = 1; i < 8; i++) r += sh8[i];
    __syncthreads();
    return r;
}

// ---------------- u update: one block per (b,q) row; float4 loads ----------
__global__ void u_update(const float* __restrict__ filt) {
    const int row = blockIdx.x;
    const int b = row >> 10;
    const float* crow = g_cost + (size_t)row * TT;
    const float* vb = g_v + b * TT;
    const float* fb = filt + b * TT;
    const float fc = 2.0f * __uint_as_float(g_maxbits);
    const int tid = threadIdx.x;
    const int t0 = tid * 4;

    __shared__ float sh8[8];

    float4 c = *(const float4*)(crow + t0);
    float4 f = *(const float4*)(fb + t0);
    float4 v = *(const float4*)(vb + t0);

    float a[4];
    a[0] = (v.x - ((f.x <= 0.0f) ? fc : c.x)) * INV_EPS;
    a[1] = (v.y - ((f.y <= 0.0f) ? fc : c.y)) * INV_EPS;
    a[2] = (v.z - ((f.z <= 0.0f) ? fc : c.z)) * INV_EPS;
    a[3] = (v.w - ((f.w <= 0.0f) ? fc : c.w)) * INV_EPS;

    float m = fmaxf(fmaxf(a[0], a[1]), fmaxf(a[2], a[3]));
    m = block_reduce_max(m, sh8);
    float s = __expf(a[0] - m) + __expf(a[1] - m) + __expf(a[2] - m) + __expf(a[3] - m);
    s = block_reduce_sum(s, sh8);
    if (tid == 0) g_u[row] = -EPS * (__logf(s) + m);
}

// ---------------- v update: block (32,8), lane -> 2 consecutive t ---------
__global__ void v_update(const float* __restrict__ filt) {
    const int b = blockIdx.y;
    const int lane = threadIdx.x;
    const int wy = threadIdx.y;
    const int t = blockIdx.x * 64 + lane * 2;
    const float fc = 2.0f * __uint_as_float(g_maxbits);
    float2 fv = *(const float2*)(filt + b * TT + t);
    const bool f0 = (fv.x <= 0.0f), f1 = (fv.y <= 0.0f);
    const float* base = g_cost + ((size_t)b * QQ) * TT + t;
    const float* ub = g_u + b * QQ;

    float m0 = -INFINITY, m1 = -INFINITY, s0 = 0.0f, s1 = 0.0f;
    for (int q0 = wy * 4; q0 < QQ; q0 += 32) {
        float2 c0 = *(const float2*)(base + (size_t)(q0 + 0) * TT);
        float2 c1 = *(const float2*)(base + (size_t)(q0 + 1) * TT);
        float2 c2 = *(const float2*)(base + (size_t)(q0 + 2) * TT);
        float2 c3 = *(const float2*)(base + (size_t)(q0 + 3) * TT);
        float u0 = ub[q0 + 0], u1 = ub[q0 + 1], u2 = ub[q0 + 2], u3 = ub[q0 + 3];
        float2 cc[4] = {c0, c1, c2, c3};
        float uu[4] = {u0, u1, u2, u3};
#pragma unroll
        for (int k = 0; k < 4; k++) {
            float ax = (uu[k] - (f0 ? fc : cc[k].x)) * INV_EPS;
            float ay = (uu[k] - (f1 ? fc : cc[k].y)) * INV_EPS;
            if (ax > m0) { s0 = s0 * __expf(m0 - ax) + 1.0f; m0 = ax; }
            else         { s0 += __expf(ax - m0); }
            if (ay > m1) { s1 = s1 * __expf(m1 - ay) + 1.0f; m1 = ay; }
            else         { s1 += __expf(ay - m1); }
        }
    }

    __shared__ float sm[8][64];
    __shared__ float ss[8][64];
    sm[wy][lane * 2] = m0;
    sm[wy][lane * 2 + 1] = m1;
    ss[wy][lane * 2] = s0;
    ss[wy][lane * 2 + 1] = s1;
    __syncthreads();
    if (wy == 0) {
        float M0 = m0, S0 = s0, M1 = m1, S1 = s1;
#pragma unroll
        for (int w = 1; w < 8; w++) {
            float m2 = sm[w][lane * 2], s2 = ss[w][lane * 2];
            if (m2 > M0) { S0 = S0 * __expf(M0 - m2) + s2; M0 = m2; }
            else         { S0 += s2 * __expf(m2 - M0); }
            float m3 = sm[w][lane * 2 + 1], s3 = ss[w][lane * 2 + 1];
            if (m3 > M1) { S1 = S1 * __expf(M1 - m3) + s3; M1 = m3; }
            else         { S1 += s3 * __expf(m3 - M1); }
        }
        float2 out;
        out.x = -EPS * (__logf(S0) + M0);
        out.y = -EPS * (__logf(S1) + M1);
        *(float2*)(g_v + b * TT + t) = out;
    }
}

// ---------------- final: P = exp((u+v-c)/eps), argmax_t (first max) ------
__global__ void p_argmax_kernel(const float* __restrict__ filt,
                                float* __restrict__ outP,
                                float* __restrict__ outIdx) {
    const int row = blockIdx.x;
    const int b = row >> 10;
    const float* crow = g_cost + (size_t)row * TT;
    const float* vb = g_v + b * TT;
    const float* fb = filt + b * TT;
    const float fc = 2.0f * __uint_as_float(g_maxbits);
    const float u = g_u[row];
    const int tid = threadIdx.x;
    const int t0 = tid * 4;

    float4 c = *(const float4*)(crow + t0);
    float4 f = *(const float4*)(fb + t0);
    float4 v = *(const float4*)(vb + t0);

    float4 p;
    p.x = __expf((u + v.x - ((f.x <= 0.0f) ? fc : c.x)) * INV_EPS);
    p.y = __expf((u + v.y - ((f.y <= 0.0f) ? fc : c.y)) * INV_EPS);
    p.z = __expf((u + v.z - ((f.z <= 0.0f) ? fc : c.z)) * INV_EPS);
    p.w = __expf((u + v.w - ((f.w <= 0.0f) ? fc : c.w)) * INV_EPS);
    if (outP) *(float4*)(outP + (size_t)row * TT + t0) = p;

    float bestv = p.x;
    int besti = t0;
    if (p.y > bestv) { bestv = p.y; besti = t0 + 1; }
    if (p.z > bestv) { bestv = p.z; besti = t0 + 2; }
    if (p.w > bestv) { bestv = p.w; besti = t0 + 3; }

    __shared__ float sv[256];
    __shared__ int si[256];
    sv[tid] = bestv;
    si[tid] = besti;
    __syncthreads();
#pragma unroll
    for (int st = 128; st > 0; st >>= 1) {
        if (tid < st) {
            float v2 = sv[tid + st];
            int i2 = si[tid + st];
            if (v2 > sv[tid] || (v2 == sv[tid] && i2 < si[tid])) {
                sv[tid] = v2;
                si[tid] = i2;
            }
        }
        __syncthreads();
    }
    if (tid == 0 && outIdx) outIdx[row] = (float)si[0];
}

// ---------------- launch ----------------
extern "C" void kernel_launch(void* const* d_in, const int* in_sizes, int n_in,
                              void* d_out, int out_size) {
    const float* preds = (const float*)d_in[0];
    const float* tgts = (const float*)d_in[1];
    const float* filt = (const float*)d_in[2];
    float* out = (float*)d_out;

    const int NP = BB * QQ * TT;
    const int NI = BB * QQ;
    float* outIdx = nullptr;
    float* outP = nullptr;
    if (out_size == NP + NI) { outIdx = out; outP = out + NI; }
    else if (out_size == NP) { outP = out; }
    else if (out_size == NI) { outIdx = out; }
    else { outIdx = out; outP = out + NI; }

    cudaFuncSetAttribute(cost_mma_kernel,
                         cudaFuncAttributeMaxDynamicSharedMemorySize, SM_TOTAL);

    init_kernel<<<(BB * QQ + 255) / 256, 256>>>();
    {
        const int nwarps = 2 * BB * QQ;
        split_norms_kernel<<<(nwarps * 32 + 255) / 256, 256>>>(preds, tgts);
    }
    cost_mma_kernel<<<dim3(TT / 128, QQ / 128, BB), 256, SM_TOTAL>>>();
    for (int it = 0; it < N_ITERS; it++) {
        u_update<<<BB * QQ, 256>>>(filt);
        v_update<<<dim3(TT / 64, BB), dim3(32, 8)>>>(filt);
    }
    p_argmax_kernel<<<BB * QQ, 256>>>(filt, outP, outIdx);
}

// round 5
// speedup vs baseline: 1.5790x; 1.2439x over previous
#include <cuda_runtime.h>
#include <cuda_bf16.h>
#include <math.h>
#include <stdint.h>

#define BB 16
#define QQ 1024
#define TT 1024
#define DD 256
#define EPS 0.1f
#define INV_EPS 10.0f
#define N_ITERS 5
#define BIGNEG (-1e30f)

#define K3 768
#define KC 64
#define STAGES 12

// ---------------- device scratch ----------------
__device__ float g_cost[(size_t)BB * QQ * TT];        // full cost (GEMM out)
__device__ float g_costp[(size_t)BB * QQ * TT];       // packed cost (unfiltered cols)
__device__ __nv_bfloat16 g_A3[(size_t)BB * QQ * K3];
__device__ __nv_bfloat16 g_B3[(size_t)BB * TT * K3];
__device__ float g_u[BB * QQ];
__device__ float g_vp[BB * TT];     // v over packed (unfiltered) columns
__device__ float g_vf[BB];          // v for filtered columns (scalar per batch)
__device__ float g_x2[BB * QQ];
__device__ float g_y2[BB * TT];
__device__ int g_pref[BB * TT];     // exclusive prefix of unfiltered flags
__device__ int g_colidx[BB * TT];   // packed idx -> original t
__device__ int g_nf[BB];            // # unfiltered columns
__device__ int g_nfilt[BB];         // # filtered columns
__device__ int g_f0[BB];            // first filtered t (TT if none)
__device__ unsigned int g_maxbits;

// ---------------- PTX helpers (baseline sm_80+) ----------------
__device__ __forceinline__ uint32_t smem_to_u32(const void* p) {
    uint32_t a;
    asm("{ .reg .u64 t; cvta.to.shared.u64 t, %1; cvt.u32.u64 %0, t; }"
        : "=r"(a) : "l"(p));
    return a;
}
#define CP_ASYNC16(dst, src) \
    asm volatile("cp.async.cg.shared.global [%0], [%1], 16;" :: "r"(dst), "l"(src))
#define CP_COMMIT() asm volatile("cp.async.commit_group;")
#define CP_WAIT1() asm volatile("cp.async.wait_group 1;")
#define CP_WAIT0() asm volatile("cp.async.wait_group 0;")

__device__ __forceinline__ void ldsm_x4(uint32_t& r0, uint32_t& r1, uint32_t& r2,
                                        uint32_t& r3, uint32_t addr) {
    asm volatile("ldmatrix.sync.aligned.m8n8.x4.shared.b16 {%0,%1,%2,%3}, [%4];"
                 : "=r"(r0), "=r"(r1), "=r"(r2), "=r"(r3) : "r"(addr));
}
__device__ __forceinline__ void mma16816(float* d, const uint32_t* a, const uint32_t* b) {
    asm volatile(
        "mma.sync.aligned.m16n8k16.row.col.f32.bf16.bf16.f32 "
        "{%0,%1,%2,%3}, {%4,%5,%6,%7}, {%8,%9}, {%0,%1,%2,%3};"
        : "+f"(d[0]), "+f"(d[1]), "+f"(d[2]), "+f"(d[3])
        : "r"(a[0]), "r"(a[1]), "r"(a[2]), "r"(a[3]), "r"(b[0]), "r"(b[1]));
}

// online-LSE merge: (m,s) <- (m,s) + (mc,sc), branchless, BIGNEG-safe
__device__ __forceinline__ void lse_merge(float& m, float& s, float mc, float sc) {
    float M = fmaxf(m, mc);
    s = s * __expf(m - M) + sc * __expf(mc - M);
    m = M;
}

// ---------------- init ----------------
__global__ void init_kernel() {
    int i = blockIdx.x * blockDim.x + threadIdx.x;
    if (i == 0) g_maxbits = 0u;
    if (i < BB) g_vf[i] = 0.0f;
    if (i < BB * TT) g_vp[i] = 0.0f;
}

// ---------------- scan: per-batch column metadata ----------------
__global__ void scan_kernel(const float* __restrict__ filt) {
    const int b = blockIdx.x;
    const int t = threadIdx.x;  // 1024 threads
    __shared__ int sh[1024];
    __shared__ int f0s;
    int flag = (filt[b * TT + t] <= 0.0f) ? 0 : 1;  // 1 = unfiltered (kept)
    sh[t] = flag;
    if (t == 0) f0s = TT;
    __syncthreads();
    for (int o = 1; o < 1024; o <<= 1) {
        int add = (t >= o) ? sh[t - o] : 0;
        __syncthreads();
        sh[t] += add;
        __syncthreads();
    }
    int incl = sh[t];
    int excl = incl - flag;
    g_pref[b * TT + t] = excl;
    if (flag) g_colidx[b * TT + excl] = t;
    if (!flag) atomicMin(&f0s, t);
    __syncthreads();
    if (t == 1023) {
        g_nf[b] = incl;
        g_nfilt[b] = TT - incl;
    }
    if (t == 0) g_f0[b] = f0s;
}

// ------- split fp32 -> bf16 hi/lo (3-pass) + row norms; warp/row -----
__global__ void split_norms_kernel(const float* __restrict__ preds,
                                   const float* __restrict__ tgts) {
    int gw = (blockIdx.x * blockDim.x + threadIdx.x) >> 5;
    int lane = threadIdx.x & 31;
    if (gw >= 2 * BB * QQ) return;
    bool isA = gw < BB * QQ;
    int r = isA ? gw : gw - BB * QQ;
    const float* src = (isA ? preds : tgts) + (size_t)r * DD;
    __nv_bfloat16* dst = (isA ? g_A3 : g_B3) + (size_t)r * K3;

    float s = 0.0f;
#pragma unroll
    for (int i = 0; i < 2; i++) {
        int k = lane * 8 + i * 4;
        float4 x = *(const float4*)(src + k);
        s = fmaf(x.x, x.x, s);
        s = fmaf(x.y, x.y, s);
        s = fmaf(x.z, x.z, s);
        s = fmaf(x.w, x.w, s);
        __nv_bfloat16 hx = __float2bfloat16_rn(x.x);
        __nv_bfloat16 hy = __float2bfloat16_rn(x.y);
        __nv_bfloat16 hz = __float2bfloat16_rn(x.z);
        __nv_bfloat16 hw = __float2bfloat16_rn(x.w);
        __nv_bfloat16 lx = __float2bfloat16_rn(x.x - __bfloat162float(hx));
        __nv_bfloat16 ly = __float2bfloat16_rn(x.y - __bfloat162float(hy));
        __nv_bfloat16 lz = __float2bfloat16_rn(x.z - __bfloat162float(hz));
        __nv_bfloat16 lw = __float2bfloat16_rn(x.w - __bfloat162float(hw));
        __nv_bfloat162 h01{hx, hy}, h23{hz, hw}, l01{lx, ly}, l23{lz, lw};
        *(__nv_bfloat162*)(dst + 0 * DD + k) = h01;
        *(__nv_bfloat162*)(dst + 0 * DD + k + 2) = h23;
        *(__nv_bfloat162*)(dst + 1 * DD + k) = isA ? l01 : h01;
        *(__nv_bfloat162*)(dst + 1 * DD + k + 2) = isA ? l23 : h23;
        *(__nv_bfloat162*)(dst + 2 * DD + k) = isA ? h01 : l01;
        *(__nv_bfloat162*)(dst + 2 * DD + k + 2) = isA ? h23 : l23;
    }
#pragma unroll
    for (int o = 16; o > 0; o >>= 1) s += __shfl_xor_sync(0xffffffffu, s, o);
    if (lane == 0) {
        if (isA) g_x2[r] = s;
        else g_y2[r] = s;
    }
}

// --------- cost via mma.sync bf16-split GEMM: CTA = 128x128 tile ------------
#define SM_TOTAL 65536
__global__ void __launch_bounds__(256)
cost_mma_kernel() {
    extern __shared__ char smem[];
    const uint32_t sb = smem_to_u32(smem);
    const int b = blockIdx.z;
    const int m_base = blockIdx.y * 128;
    const int n_base = blockIdx.x * 128;
    const int tid = threadIdx.x;
    const int wid = tid >> 5;
    const int lane = tid & 31;
    const int warp_m = wid >> 2;
    const int warp_n = wid & 3;

    const __nv_bfloat16* Ag = g_A3 + (size_t)(b * QQ + m_base) * K3;
    const __nv_bfloat16* Bg = g_B3 + (size_t)(b * TT + n_base) * K3;

    auto load_stage = [&](int s, int buf) {
        uint32_t abase = sb + (uint32_t)buf * 32768u;
        uint32_t bbase = abase + 16384u;
#pragma unroll
        for (int v = 0; v < 4; v++) {
            int idx = tid + v * 256;
            int r = idx >> 3;
            int g = idx & 7;
            uint32_t off = (uint32_t)(r * 128 + ((g ^ (r & 7)) << 4));
            CP_ASYNC16(abase + off, Ag + (size_t)r * K3 + s * KC + g * 8);
            CP_ASYNC16(bbase + off, Bg + (size_t)r * K3 + s * KC + g * 8);
        }
    };

    const int laneA_r = (lane & 7) + ((lane >> 3) & 1) * 8;
    const int khA = (lane >> 4) & 1;
    const int laneB_r = (lane & 7) + ((lane >> 4) & 1) * 8;
    const int khB = (lane >> 3) & 1;
    const int xorA = laneA_r & 7;
    const int xorB = laneB_r & 7;

    float acc[4][4][4];
#pragma unroll
    for (int i = 0; i < 4; i++)
#pragma unroll
        for (int j = 0; j < 4; j++)
#pragma unroll
            for (int e = 0; e < 4; e++) acc[i][j][e] = 0.0f;

    load_stage(0, 0);
    CP_COMMIT();

    for (int s = 0; s < STAGES; s++) {
        const int buf = s & 1;
        if (s + 1 < STAGES) {
            load_stage(s + 1, buf ^ 1);
            CP_COMMIT();
            CP_WAIT1();
        } else {
            CP_WAIT0();
        }
        __syncthreads();

        uint32_t abase = sb + (uint32_t)buf * 32768u;
        uint32_t bbase = abase + 16384u;
#pragma unroll
        for (int kq = 0; kq < 4; kq++) {
            uint32_t afrag[4][4];
            uint32_t bfrag[4][2];
#pragma unroll
            for (int im = 0; im < 4; im++) {
                int row = warp_m * 64 + im * 16 + laneA_r;
                uint32_t addr = abase + (uint32_t)(row * 128 + (((khA + 2 * kq) ^ xorA) << 4));
                ldsm_x4(afrag[im][0], afrag[im][1], afrag[im][2], afrag[im][3], addr);
            }
#pragma unroll
            for (int ip = 0; ip < 2; ip++) {
                int row = warp_n * 32 + ip * 16 + laneB_r;
                uint32_t addr = bbase + (uint32_t)(row * 128 + (((khB + 2 * kq) ^ xorB) << 4));
                ldsm_x4(bfrag[ip * 2][0], bfrag[ip * 2][1],
                        bfrag[ip * 2 + 1][0], bfrag[ip * 2 + 1][1], addr);
            }
#pragma unroll
            for (int im = 0; im < 4; im++)
#pragma unroll
                for (int in = 0; in < 4; in++)
                    mma16816(acc[im][in], afrag[im], bfrag[in]);
        }
        __syncthreads();
    }

    const float* x2p = g_x2 + b * QQ + m_base;
    const float* y2p = g_y2 + b * TT + n_base;
    float tmax = 0.0f;
#pragma unroll
    for (int im = 0; im < 4; im++) {
        int m0 = warp_m * 64 + im * 16 + (lane >> 2);
        float xi0 = x2p[m0];
        float xi1 = x2p[m0 + 8];
#pragma unroll
        for (int in = 0; in < 4; in++) {
            int n0 = warp_n * 32 + in * 8 + (lane & 3) * 2;
            float y0 = y2p[n0];
            float y1 = y2p[n0 + 1];
            float c00 = sqrtf(fmaxf(fmaf(-2.0f, acc[im][in][0], xi0 + y0), 0.0f));
            float c01 = sqrtf(fmaxf(fmaf(-2.0f, acc[im][in][1], xi0 + y1), 0.0f));
            float c10 = sqrtf(fmaxf(fmaf(-2.0f, acc[im][in][2], xi1 + y0), 0.0f));
            float c11 = sqrtf(fmaxf(fmaf(-2.0f, acc[im][in][3], xi1 + y1), 0.0f));
            tmax = fmaxf(tmax, fmaxf(fmaxf(c00, c01), fmaxf(c10, c11)));
            size_t g0 = ((size_t)(b * QQ + m_base + m0)) * TT + n_base + n0;
            size_t g1 = ((size_t)(b * QQ + m_base + m0 + 8)) * TT + n_base + n0;
            *(float2*)(g_cost + g0) = make_float2(c00, c01);
            *(float2*)(g_cost + g1) = make_float2(c10, c11);
        }
    }

    __shared__ unsigned int smax;
    if (tid == 0) smax = 0u;
    __syncthreads();
#pragma unroll
    for (int o = 16; o > 0; o >>= 1)
        tmax = fmaxf(tmax, __shfl_xor_sync(0xffffffffu, tmax, o));
    if (lane == 0) atomicMax(&smax, __float_as_uint(tmax));
    __syncthreads();
    if (tid == 0) atomicMax(&g_maxbits, smax);
}

// ---------------- pack: compact unfiltered columns; pad +inf ----------------
__global__ void pack_kernel(const float* __restrict__ filt) {
    const int row = blockIdx.x;     // b*QQ + q
    const int b = row >> 10;
    const int tid = threadIdx.x;
    const float* src = g_cost + (size_t)row * TT;
    float* dst = g_costp + (size_t)row * TT;
    const int nf = g_nf[b];
    const int nfpad = (nf + 127) & ~127;
    const float INF = __int_as_float(0x7f800000);
#pragma unroll
    for (int i = 0; i < 4; i++) {
        int t = tid + i * 256;
        float c = src[t];
        float f = filt[b * TT + t];
        int p = g_pref[b * TT + t];
        if (f > 0.0f) dst[p] = c;
    }
    for (int p = nf + tid; p < nfpad; p += 256) dst[p] = INF;
}

// ---------------- u update: warp per row over packed columns ----------------
__global__ void u_update_p() {
    const int gw = (blockIdx.x * blockDim.x + threadIdx.x) >> 5;  // row
    const int lane = threadIdx.x & 31;
    if (gw >= BB * QQ) return;
    const int b = gw >> 10;
    const float* crow = g_costp + (size_t)gw * TT;
    const float* vp = g_vp + b * TT;
    const int nf = g_nf[b];
    const int nk = (nf + 127) >> 7;     // 128-wide chunks
    const float fc = 2.0f * __uint_as_float(g_maxbits);
    const float vf = g_vf[b];
    const float nfl = (float)g_nfilt[b];

    float m = BIGNEG, s = 0.0f;
    int k = 0;
    for (; k + 1 < nk; k += 2) {
        int j0 = k * 128 + lane * 4;
        int j1 = j0 + 128;
        float4 c0 = *(const float4*)(crow + j0);
        float4 v0 = *(const float4*)(vp + j0);
        float4 c1 = *(const float4*)(crow + j1);
        float4 v1 = *(const float4*)(vp + j1);
        float a0 = (v0.x - c0.x) * INV_EPS, a1 = (v0.y - c0.y) * INV_EPS;
        float a2 = (v0.z - c0.z) * INV_EPS, a3 = (v0.w - c0.w) * INV_EPS;
        float b0 = (v1.x - c1.x) * INV_EPS, b1 = (v1.y - c1.y) * INV_EPS;
        float b2 = (v1.z - c1.z) * INV_EPS, b3 = (v1.w - c1.w) * INV_EPS;
        float mc = fmaxf(fmaxf(fmaxf(a0, a1), fmaxf(a2, a3)),
                         fmaxf(fmaxf(b0, b1), fmaxf(b2, b3)));
        mc = fmaxf(mc, BIGNEG);
        float sc = __expf(a0 - mc) + __expf(a1 - mc) + __expf(a2 - mc) + __expf(a3 - mc) +
                   __expf(b0 - mc) + __expf(b1 - mc) + __expf(b2 - mc) + __expf(b3 - mc);
        lse_merge(m, s, mc, sc);
    }
    if (k < nk) {
        int j0 = k * 128 + lane * 4;
        float4 c0 = *(const float4*)(crow + j0);
        float4 v0 = *(const float4*)(vp + j0);
        float a0 = (v0.x - c0.x) * INV_EPS, a1 = (v0.y - c0.y) * INV_EPS;
        float a2 = (v0.z - c0.z) * INV_EPS, a3 = (v0.w - c0.w) * INV_EPS;
        float mc = fmaxf(fmaxf(fmaxf(a0, a1), fmaxf(a2, a3)), BIGNEG);
        float sc = __expf(a0 - mc) + __expf(a1 - mc) + __expf(a2 - mc) + __expf(a3 - mc);
        lse_merge(m, s, mc, sc);
    }
#pragma unroll
    for (int o = 16; o > 0; o >>= 1) {
        float m2 = __shfl_xor_sync(0xffffffffu, m, o);
        float s2 = __shfl_xor_sync(0xffffffffu, s, o);
        lse_merge(m, s, m2, s2);
    }
    // merge filtered-column constant term: nfilt * exp((vf - fc)/eps)
    lse_merge(m, s, (vf - fc) * INV_EPS, nfl);
    if (lane == 0) g_u[gw] = -EPS * (__logf(s) + m);
}

// ---------------- vf: v for filtered columns (scalar per batch) -------------
__global__ void vf_kernel() {
    const int b = blockIdx.x;
    const int tid = threadIdx.x;
    const float* ub = g_u + b * QQ;
    __shared__ float sh8[8];
    float4 u4 = *(const float4*)(ub + tid * 4);
    float a0 = u4.x * INV_EPS, a1 = u4.y * INV_EPS;
    float a2 = u4.z * INV_EPS, a3 = u4.w * INV_EPS;
    float m = fmaxf(fmaxf(a0, a1), fmaxf(a2, a3));
#pragma unroll
    for (int o = 16; o > 0; o >>= 1) m = fmaxf(m, __shfl_xor_sync(0xffffffffu, m, o));
    int w = tid >> 5;
    if ((tid & 31) == 0) sh8[w] = m;
    __syncthreads();
    float M = sh8[0];
#pragma unroll
    for (int i = 1; i < 8; i++) M = fmaxf(M, sh8[i]);
    __syncthreads();
    float s = __expf(a0 - M) + __expf(a1 - M) + __expf(a2 - M) + __expf(a3 - M);
#pragma unroll
    for (int o = 16; o > 0; o >>= 1) s += __shfl_xor_sync(0xffffffffu, s, o);
    if ((tid & 31) == 0) sh8[w] = s;
    __syncthreads();
    if (tid == 0) {
        float S = sh8[0];
#pragma unroll
        for (int i = 1; i < 8; i++) S += sh8[i];
        const float fc = 2.0f * __uint_as_float(g_maxbits);
        // vf = -eps*(LSE(u*10) - 10*fc) = -eps*LSE(u*10) + fc
        g_vf[b] = -EPS * (__logf(S) + M) + fc;
    }
}

// ---------------- v update over packed columns: block (32,8) ---------------
__global__ void v_update_p() {
    const int b = blockIdx.y;
    const int lane = threadIdx.x;
    const int wy = threadIdx.y;
    const int nf = g_nf[b];
    const int nfpad = (nf + 127) & ~127;
    const int jb = blockIdx.x * 128;
    if (jb >= nfpad) return;
    const int j = jb + lane * 4;
    const float* base = g_costp + ((size_t)b * QQ) * TT;
    const float* ub = g_u + b * QQ;

    float m[4] = {BIGNEG, BIGNEG, BIGNEG, BIGNEG};
    float s[4] = {0.0f, 0.0f, 0.0f, 0.0f};

    for (int q0 = wy * 8; q0 < QQ; q0 += 64) {
        float4 c[8];
        float uu[8];
#pragma unroll
        for (int r = 0; r < 8; r++) {
            c[r] = *(const float4*)(base + (size_t)(q0 + r) * TT + j);
            uu[r] = ub[q0 + r];
        }
#pragma unroll
        for (int e = 0; e < 4; e++) {
            float a[8];
#pragma unroll
            for (int r = 0; r < 8; r++) {
                float ce = (e == 0) ? c[r].x : (e == 1) ? c[r].y : (e == 2) ? c[r].z : c[r].w;
                a[r] = (uu[r] - ce) * INV_EPS;
            }
            float mc = a[0];
#pragma unroll
            for (int r = 1; r < 8; r++) mc = fmaxf(mc, a[r]);
            mc = fmaxf(mc, BIGNEG);
            float sc = 0.0f;
#pragma unroll
            for (int r = 0; r < 8; r++) sc += __expf(a[r] - mc);
            lse_merge(m[e], s[e], mc, sc);
        }
    }

    __shared__ float sm[8][128];
    __shared__ float ss[8][128];
#pragma unroll
    for (int e = 0; e < 4; e++) {
        sm[wy][lane * 4 + e] = m[e];
        ss[wy][lane * 4 + e] = s[e];
    }
    __syncthreads();
    if (wy == 0) {
#pragma unroll
        for (int e = 0; e < 4; e++) {
            float M = m[e], S = s[e];
#pragma unroll
            for (int w = 1; w < 8; w++)
                lse_merge(M, S, sm[w][lane * 4 + e], ss[w][lane * 4 + e]);
            int jj = j + e;
            if (jj < nf) g_vp[b * TT + jj] = -EPS * (__logf(S) + M);
        }
    }
}

// ---------------- final: unpack P row + argmax (first max) ----------------
__global__ void p_argmax_kernel(float* __restrict__ outP,
                                float* __restrict__ outIdx) {
    const int row = blockIdx.x;
    const int b = row >> 10;
    const int tid = threadIdx.x;
    const float* crow = g_costp + (size_t)row * TT;
    const float* vp = g_vp + b * TT;
    const int* cidx = g_colidx + b * TT;
    const int nf = g_nf[b];
    const int nfilt = g_nfilt[b];
    const int f0 = g_f0[b];
    const float fc = 2.0f * __uint_as_float(g_maxbits);
    const float vf = g_vf[b];
    const float u = g_u[row];
    const float pconst = __expf((u + vf - fc) * INV_EPS);

    __shared__ float rowbuf[1024];
    __shared__ float sv[256];
    __shared__ int si[256];

#pragma unroll
    for (int i = 0; i < 4; i++) rowbuf[tid + i * 256] = pconst;
    __syncthreads();

    float best = BIGNEG;
    int bidx = 0x7fffffff;
#pragma unroll
    for (int i = 0; i < 4; i++) {
        int j = tid + i * 256;
        if (j < nf) {
            float p = __expf((u + vp[j] - crow[j]) * INV_EPS);
            int t = cidx[j];
            rowbuf[t] = p;
            if (p > best || (p == best && t < bidx)) { best = p; bidx = t; }
        }
    }
    sv[tid] = best;
    si[tid] = bidx;
    __syncthreads();
#pragma unroll
    for (int st = 128; st > 0; st >>= 1) {
        if (tid < st) {
            float v2 = sv[tid + st];
            int i2 = si[tid + st];
            if (v2 > sv[tid] || (v2 == sv[tid] && i2 < si[tid])) {
                sv[tid] = v2;
                si[tid] = i2;
            }
        }
        __syncthreads();
    }

    if (outP) {
#pragma unroll
        for (int i = 0; i < 2; i++) {
            int j4 = (tid + i * 256) * 2;
            float2 o = make_float2(rowbuf[j4], rowbuf[j4 + 1]);
            *(float2*)(outP + (size_t)row * TT + j4) = o;
        }
    }
    if (tid == 0 && outIdx) {
        float bv = sv[0];
        int bi = si[0];
        if (nfilt > 0) {
            if (pconst > bv || (pconst == bv && f0 < bi)) { bv = pconst; bi = f0; }
        }
        outIdx[row] = (float)bi;
    }
}

// ---------------- launch ----------------
extern "C" void kernel_launch(void* const* d_in, const int* in_sizes, int n_in,
                              void* d_out, int out_size) {
    const float* preds = (const float*)d_in[0];
    const float* tgts = (const float*)d_in[1];
    const float* filt = (const float*)d_in[2];
    float* out = (float*)d_out;

    const int NP = BB * QQ * TT;
    const int NI = BB * QQ;
    float* outIdx = nullptr;
    float* outP = nullptr;
    if (out_size == NP + NI) { outIdx = out; outP = out + NI; }
    else if (out_size == NP) { outP = out; }
    else if (out_size == NI) { outIdx = out; }
    else { outIdx = out; outP = out + NI; }

    cudaFuncSetAttribute(cost_mma_kernel,
                         cudaFuncAttributeMaxDynamicSharedMemorySize, SM_TOTAL);

    init_kernel<<<(BB * TT + 255) / 256, 256>>>();
    scan_kernel<<<BB, 1024>>>(filt);
    {
        const int nwarps = 2 * BB * QQ;
        split_norms_kernel<<<(nwarps * 32 + 255) / 256, 256>>>(preds, tgts);
    }
    cost_mma_kernel<<<dim3(TT / 128, QQ / 128, BB), 256, SM_TOTAL>>>();
    pack_kernel<<<BB * QQ, 256>>>(filt);
    for (int it = 0; it < N_ITERS; it++) {
        u_update_p<<<(BB * QQ * 32 + 255) / 256, 256>>>();
        vf_kernel<<<BB, 256>>>();
        v_update_p<<<dim3(TT / 128, BB), dim3(32, 8)>>>();
    }
    p_argmax_kernel<<<BB * QQ, 256>>>(outP, outIdx);
}

// round 6
// speedup vs baseline: 1.7739x; 1.1235x over previous
#include <cuda_runtime.h>
#include <cuda_bf16.h>
#include <math.h>
#include <stdint.h>

#define BB 16
#define QQ 1024
#define TT 1024
#define DD 256
#define EPS 0.1f
#define INV_EPS 10.0f
#define N_ITERS 5
#define BIGNEG (-1e30f)

#define K3 768
#define KC 64
#define STAGES 12

// ---------------- device scratch ----------------
__device__ float g_costp[(size_t)BB * QQ * TT];   // packed cost (unfiltered cols)
__device__ __nv_bfloat16 g_A3[(size_t)BB * QQ * K3];
__device__ __nv_bfloat16 g_B3[(size_t)BB * TT * K3];
__device__ float g_u[BB * QQ];
__device__ float g_vp[BB * TT];
__device__ float g_vf[BB];
__device__ float g_vpm[BB * 4 * TT];   // split-K v partial max
__device__ float g_vps[BB * 4 * TT];   // split-K v partial sum
__device__ float g_x2[BB * QQ];
__device__ float g_y2[BB * TT];
__device__ int g_pref[BB * TT];
__device__ int g_colidx[BB * TT];
__device__ int g_nf[BB];
__device__ int g_nfilt[BB];
__device__ int g_f0[BB];
__device__ unsigned int g_maxbits;

// ---------------- PTX helpers (baseline sm_80+) ----------------
__device__ __forceinline__ uint32_t smem_to_u32(const void* p) {
    uint32_t a;
    asm("{ .reg .u64 t; cvta.to.shared.u64 t, %1; cvt.u32.u64 %0, t; }"
        : "=r"(a) : "l"(p));
    return a;
}
#define CP_ASYNC16(dst, src) \
    asm volatile("cp.async.cg.shared.global [%0], [%1], 16;" :: "r"(dst), "l"(src))
#define CP_COMMIT() asm volatile("cp.async.commit_group;")
#define CP_WAIT1() asm volatile("cp.async.wait_group 1;")
#define CP_WAIT0() asm volatile("cp.async.wait_group 0;")

__device__ __forceinline__ void ldsm_x4(uint32_t& r0, uint32_t& r1, uint32_t& r2,
                                        uint32_t& r3, uint32_t addr) {
    asm volatile("ldmatrix.sync.aligned.m8n8.x4.shared.b16 {%0,%1,%2,%3}, [%4];"
                 : "=r"(r0), "=r"(r1), "=r"(r2), "=r"(r3) : "r"(addr));
}
__device__ __forceinline__ void mma16816(float* d, const uint32_t* a, const uint32_t* b) {
    asm volatile(
        "mma.sync.aligned.m16n8k16.row.col.f32.bf16.bf16.f32 "
        "{%0,%1,%2,%3}, {%4,%5,%6,%7}, {%8,%9}, {%0,%1,%2,%3};"
        : "+f"(d[0]), "+f"(d[1]), "+f"(d[2]), "+f"(d[3])
        : "r"(a[0]), "r"(a[1]), "r"(a[2]), "r"(a[3]), "r"(b[0]), "r"(b[1]));
}
__device__ __forceinline__ void lse_merge(float& m, float& s, float mc, float sc) {
    float M = fmaxf(m, mc);
    s = s * __expf(m - M) + sc * __expf(mc - M);
    m = M;
}

// ---------------- init ----------------
__global__ void init_kernel() {
    int i = blockIdx.x * blockDim.x + threadIdx.x;
    if (i == 0) g_maxbits = 0u;
    if (i < BB) g_vf[i] = 0.0f;
    if (i < BB * TT) g_vp[i] = 0.0f;
}

// ---------------- scan: per-batch column metadata ----------------
__global__ void scan_kernel(const float* __restrict__ filt) {
    const int b = blockIdx.x;
    const int t = threadIdx.x;
    __shared__ int sh[1024];
    __shared__ int f0s;
    int flag = (filt[b * TT + t] <= 0.0f) ? 0 : 1;
    sh[t] = flag;
    if (t == 0) f0s = TT;
    __syncthreads();
    for (int o = 1; o < 1024; o <<= 1) {
        int add = (t >= o) ? sh[t - o] : 0;
        __syncthreads();
        sh[t] += add;
        __syncthreads();
    }
    int incl = sh[t];
    int excl = incl - flag;
    g_pref[b * TT + t] = excl;
    if (flag) g_colidx[b * TT + excl] = t;
    if (!flag) atomicMin(&f0s, t);
    __syncthreads();
    if (t == 1023) {
        g_nf[b] = incl;
        g_nfilt[b] = TT - incl;
    }
    if (t == 0) g_f0[b] = f0s;
}

// ------- split fp32 -> bf16 hi/lo (3-pass) + row norms; warp/row -----
__global__ void split_norms_kernel(const float* __restrict__ preds,
                                   const float* __restrict__ tgts) {
    int gw = (blockIdx.x * blockDim.x + threadIdx.x) >> 5;
    int lane = threadIdx.x & 31;
    if (gw >= 2 * BB * QQ) return;
    bool isA = gw < BB * QQ;
    int r = isA ? gw : gw - BB * QQ;
    const float* src = (isA ? preds : tgts) + (size_t)r * DD;
    __nv_bfloat16* dst = (isA ? g_A3 : g_B3) + (size_t)r * K3;

    float s = 0.0f;
#pragma unroll
    for (int i = 0; i < 2; i++) {
        int k = lane * 8 + i * 4;
        float4 x = *(const float4*)(src + k);
        s = fmaf(x.x, x.x, s);
        s = fmaf(x.y, x.y, s);
        s = fmaf(x.z, x.z, s);
        s = fmaf(x.w, x.w, s);
        __nv_bfloat16 hx = __float2bfloat16_rn(x.x);
        __nv_bfloat16 hy = __float2bfloat16_rn(x.y);
        __nv_bfloat16 hz = __float2bfloat16_rn(x.z);
        __nv_bfloat16 hw = __float2bfloat16_rn(x.w);
        __nv_bfloat16 lx = __float2bfloat16_rn(x.x - __bfloat162float(hx));
        __nv_bfloat16 ly = __float2bfloat16_rn(x.y - __bfloat162float(hy));
        __nv_bfloat16 lz = __float2bfloat16_rn(x.z - __bfloat162float(hz));
        __nv_bfloat16 lw = __float2bfloat16_rn(x.w - __bfloat162float(hw));
        __nv_bfloat162 h01{hx, hy}, h23{hz, hw}, l01{lx, ly}, l23{lz, lw};
        *(__nv_bfloat162*)(dst + 0 * DD + k) = h01;
        *(__nv_bfloat162*)(dst + 0 * DD + k + 2) = h23;
        *(__nv_bfloat162*)(dst + 1 * DD + k) = isA ? l01 : h01;
        *(__nv_bfloat162*)(dst + 1 * DD + k + 2) = isA ? l23 : h23;
        *(__nv_bfloat162*)(dst + 2 * DD + k) = isA ? h01 : l01;
        *(__nv_bfloat162*)(dst + 2 * DD + k + 2) = isA ? h23 : l23;
    }
#pragma unroll
    for (int o = 16; o > 0; o >>= 1) s += __shfl_xor_sync(0xffffffffu, s, o);
    if (lane == 0) {
        if (isA) g_x2[r] = s;
        else g_y2[r] = s;
    }
}

// --------- cost GEMM + fused pack: CTA = 128x128 tile -----------------------
// dyn smem: GEMM phase = 4x16KB buffers (64KB); epilogue reuses as
// float tile[128][132] (67584 B). SM_TOTAL = 67584.
#define SM_TOTAL 67584
__global__ void __launch_bounds__(256)
cost_mma_kernel(const float* __restrict__ filt) {
    extern __shared__ char smem[];
    const uint32_t sb = smem_to_u32(smem);
    const int b = blockIdx.z;
    const int m_base = blockIdx.y * 128;
    const int n_base = blockIdx.x * 128;
    const int tid = threadIdx.x;
    const int wid = tid >> 5;
    const int lane = tid & 31;
    const int warp_m = wid >> 2;
    const int warp_n = wid & 3;

    __shared__ int s_keptloc[128];
    __shared__ int s_cnt;
    __shared__ int s_pbase;
    __shared__ unsigned int smax;

    if (tid == 0) {
        int pb = g_pref[b * TT + n_base];
        s_pbase = pb;
        int pend = (n_base + 128 < TT) ? g_pref[b * TT + n_base + 128] : g_nf[b];
        s_cnt = pend - pb;
        smax = 0u;
    }

    const __nv_bfloat16* Ag = g_A3 + (size_t)(b * QQ + m_base) * K3;
    const __nv_bfloat16* Bg = g_B3 + (size_t)(b * TT + n_base) * K3;

    auto load_stage = [&](int s, int buf) {
        uint32_t abase = sb + (uint32_t)buf * 32768u;
        uint32_t bbase = abase + 16384u;
#pragma unroll
        for (int v = 0; v < 4; v++) {
            int idx = tid + v * 256;
            int r = idx >> 3;
            int g = idx & 7;
            uint32_t off = (uint32_t)(r * 128 + ((g ^ (r & 7)) << 4));
            CP_ASYNC16(abase + off, Ag + (size_t)r * K3 + s * KC + g * 8);
            CP_ASYNC16(bbase + off, Bg + (size_t)r * K3 + s * KC + g * 8);
        }
    };

    const int laneA_r = (lane & 7) + ((lane >> 3) & 1) * 8;
    const int khA = (lane >> 4) & 1;
    const int laneB_r = (lane & 7) + ((lane >> 4) & 1) * 8;
    const int khB = (lane >> 3) & 1;
    const int xorA = laneA_r & 7;
    const int xorB = laneB_r & 7;

    float acc[4][4][4];
#pragma unroll
    for (int i = 0; i < 4; i++)
#pragma unroll
        for (int j = 0; j < 4; j++)
#pragma unroll
            for (int e = 0; e < 4; e++) acc[i][j][e] = 0.0f;

    load_stage(0, 0);
    CP_COMMIT();

    for (int s = 0; s < STAGES; s++) {
        const int buf = s & 1;
        if (s + 1 < STAGES) {
            load_stage(s + 1, buf ^ 1);
            CP_COMMIT();
            CP_WAIT1();
        } else {
            CP_WAIT0();
        }
        __syncthreads();

        uint32_t abase = sb + (uint32_t)buf * 32768u;
        uint32_t bbase = abase + 16384u;
#pragma unroll
        for (int kq = 0; kq < 4; kq++) {
            uint32_t afrag[4][4];
            uint32_t bfrag[4][2];
#pragma unroll
            for (int im = 0; im < 4; im++) {
                int row = warp_m * 64 + im * 16 + laneA_r;
                uint32_t addr = abase + (uint32_t)(row * 128 + (((khA + 2 * kq) ^ xorA) << 4));
                ldsm_x4(afrag[im][0], afrag[im][1], afrag[im][2], afrag[im][3], addr);
            }
#pragma unroll
            for (int ip = 0; ip < 2; ip++) {
                int row = warp_n * 32 + ip * 16 + laneB_r;
                uint32_t addr = bbase + (uint32_t)(row * 128 + (((khB + 2 * kq) ^ xorB) << 4));
                ldsm_x4(bfrag[ip * 2][0], bfrag[ip * 2][1],
                        bfrag[ip * 2 + 1][0], bfrag[ip * 2 + 1][1], addr);
            }
#pragma unroll
            for (int im = 0; im < 4; im++)
#pragma unroll
                for (int in = 0; in < 4; in++)
                    mma16816(acc[im][in], afrag[im], bfrag[in]);
        }
        __syncthreads();
    }

    // ----- fused epilogue: cost -> smem tile; kept-col metadata -----
    if (tid < 128) {
        int t = n_base + tid;
        bool kept = filt[b * TT + t] > 0.0f;
        int p = g_pref[b * TT + t];
        if (kept) s_keptloc[p - s_pbase] = tid;   // s_pbase valid: written pre-mainloop
    }

    const float* x2p = g_x2 + b * QQ + m_base;
    const float* y2p = g_y2 + b * TT + n_base;
    float* tile = (float*)smem;    // [128][132]
    float tmax = 0.0f;
#pragma unroll
    for (int im = 0; im < 4; im++) {
        int m0 = warp_m * 64 + im * 16 + (lane >> 2);
        float xi0 = x2p[m0];
        float xi1 = x2p[m0 + 8];
#pragma unroll
        for (int in = 0; in < 4; in++) {
            int n0 = warp_n * 32 + in * 8 + (lane & 3) * 2;
            float y0 = y2p[n0];
            float y1 = y2p[n0 + 1];
            float c00 = sqrtf(fmaxf(fmaf(-2.0f, acc[im][in][0], xi0 + y0), 0.0f));
            float c01 = sqrtf(fmaxf(fmaf(-2.0f, acc[im][in][1], xi0 + y1), 0.0f));
            float c10 = sqrtf(fmaxf(fmaf(-2.0f, acc[im][in][2], xi1 + y0), 0.0f));
            float c11 = sqrtf(fmaxf(fmaf(-2.0f, acc[im][in][3], xi1 + y1), 0.0f));
            tmax = fmaxf(tmax, fmaxf(fmaxf(c00, c01), fmaxf(c10, c11)));
            tile[m0 * 132 + n0] = c00;
            tile[m0 * 132 + n0 + 1] = c01;
            tile[(m0 + 8) * 132 + n0] = c10;
            tile[(m0 + 8) * 132 + n0 + 1] = c11;
        }
    }
    __syncthreads();

    // packed coalesced stores: kept columns only
    {
        const int kept = s_cnt;
        const int pbase = s_pbase;
        for (int r = wid; r < 128; r += 8) {
            size_t dst = ((size_t)(b * QQ + m_base + r)) * TT + pbase;
            for (int j = lane; j < kept; j += 32)
                g_costp[dst + j] = tile[r * 132 + s_keptloc[j]];
        }
    }
    // +inf pad written once per (b, m-tile) by the n-tile-0 CTA
    if (blockIdx.x == 0) {
        const int nf = g_nf[b];
        const int nfpad = (nf + 127) & ~127;
        const float INF = __int_as_float(0x7f800000);
        for (int r = wid; r < 128; r += 8) {
            size_t dst = ((size_t)(b * QQ + m_base + r)) * TT;
            for (int j = nf + lane; j < nfpad; j += 32) g_costp[dst + j] = INF;
        }
    }

#pragma unroll
    for (int o = 16; o > 0; o >>= 1)
        tmax = fmaxf(tmax, __shfl_xor_sync(0xffffffffu, tmax, o));
    if (lane == 0) atomicMax(&smax, __float_as_uint(tmax));
    __syncthreads();
    if (tid == 0) atomicMax(&g_maxbits, smax);
}

// ---------------- u update: 8 rows per block, vp cached in smem -------------
__global__ void u_update_p() {
    const int row0 = blockIdx.x * 8;
    const int b = row0 >> 10;
    const int tid = threadIdx.x;
    const int w = tid >> 5;
    const int lane = tid & 31;
    const int nf = g_nf[b];
    const int nfpad = (nf + 127) & ~127;
    const int nk = nfpad >> 7;
    const float fc = 2.0f * __uint_as_float(g_maxbits);
    const float vf = g_vf[b];
    const float nfl = (float)g_nfilt[b];

    __shared__ float svp[1024];
    for (int j = tid; j < nfpad; j += 256) svp[j] = g_vp[b * TT + j] * INV_EPS;
    __syncthreads();

    const int row = row0 + w;
    const float* crow = g_costp + (size_t)row * TT;

    float m = BIGNEG, s = 0.0f;
    int k = 0;
    for (; k + 1 < nk; k += 2) {
        int j0 = k * 128 + lane * 4;
        int j1 = j0 + 128;
        float4 c0 = *(const float4*)(crow + j0);
        float4 c1 = *(const float4*)(crow + j1);
        float4 v0 = *(const float4*)(svp + j0);
        float4 v1 = *(const float4*)(svp + j1);
        float a0 = fmaf(-INV_EPS, c0.x, v0.x), a1 = fmaf(-INV_EPS, c0.y, v0.y);
        float a2 = fmaf(-INV_EPS, c0.z, v0.z), a3 = fmaf(-INV_EPS, c0.w, v0.w);
        float b0 = fmaf(-INV_EPS, c1.x, v1.x), b1 = fmaf(-INV_EPS, c1.y, v1.y);
        float b2 = fmaf(-INV_EPS, c1.z, v1.z), b3 = fmaf(-INV_EPS, c1.w, v1.w);
        float mc = fmaxf(fmaxf(fmaxf(a0, a1), fmaxf(a2, a3)),
                         fmaxf(fmaxf(b0, b1), fmaxf(b2, b3)));
        mc = fmaxf(mc, BIGNEG);
        float sc = __expf(a0 - mc) + __expf(a1 - mc) + __expf(a2 - mc) + __expf(a3 - mc) +
                   __expf(b0 - mc) + __expf(b1 - mc) + __expf(b2 - mc) + __expf(b3 - mc);
        lse_merge(m, s, mc, sc);
    }
    if (k < nk) {
        int j0 = k * 128 + lane * 4;
        float4 c0 = *(const float4*)(crow + j0);
        float4 v0 = *(const float4*)(svp + j0);
        float a0 = fmaf(-INV_EPS, c0.x, v0.x), a1 = fmaf(-INV_EPS, c0.y, v0.y);
        float a2 = fmaf(-INV_EPS, c0.z, v0.z), a3 = fmaf(-INV_EPS, c0.w, v0.w);
        float mc = fmaxf(fmaxf(fmaxf(a0, a1), fmaxf(a2, a3)), BIGNEG);
        float sc = __expf(a0 - mc) + __expf(a1 - mc) + __expf(a2 - mc) + __expf(a3 - mc);
        lse_merge(m, s, mc, sc);
    }
#pragma unroll
    for (int o = 16; o > 0; o >>= 1) {
        float m2 = __shfl_xor_sync(0xffffffffu, m, o);
        float s2 = __shfl_xor_sync(0xffffffffu, s, o);
        lse_merge(m, s, m2, s2);
    }
    lse_merge(m, s, (vf - fc) * INV_EPS, nfl);
    if (lane == 0) g_u[row] = -EPS * (__logf(s) + m);
}

// ---------------- vf: v for filtered columns (scalar per batch) -------------
__global__ void vf_kernel() {
    const int b = blockIdx.x;
    const int tid = threadIdx.x;
    const float* ub = g_u + b * QQ;
    __shared__ float sh8[8];
    float4 u4 = *(const float4*)(ub + tid * 4);
    float a0 = u4.x * INV_EPS, a1 = u4.y * INV_EPS;
    float a2 = u4.z * INV_EPS, a3 = u4.w * INV_EPS;
    float m = fmaxf(fmaxf(a0, a1), fmaxf(a2, a3));
#pragma unroll
    for (int o = 16; o > 0; o >>= 1) m = fmaxf(m, __shfl_xor_sync(0xffffffffu, m, o));
    int w = tid >> 5;
    if ((tid & 31) == 0) sh8[w] = m;
    __syncthreads();
    float M = sh8[0];
#pragma unroll
    for (int i = 1; i < 8; i++) M = fmaxf(M, sh8[i]);
    __syncthreads();
    float s = __expf(a0 - M) + __expf(a1 - M) + __expf(a2 - M) + __expf(a3 - M);
#pragma unroll
    for (int o = 16; o > 0; o >>= 1) s += __shfl_xor_sync(0xffffffffu, s, o);
    if ((tid & 31) == 0) sh8[w] = s;
    __syncthreads();
    if (tid == 0) {
        float S = sh8[0];
#pragma unroll
        for (int i = 1; i < 8; i++) S += sh8[i];
        const float fc = 2.0f * __uint_as_float(g_maxbits);
        g_vf[b] = -EPS * (__logf(S) + M) + fc;
    }
}

// ---------------- v partial: grid (8, BB, 4), block (32,8); 256 q each ------
__global__ void v_partial() {
    const int b = blockIdx.y;
    const int z = blockIdx.z;
    const int lane = threadIdx.x;
    const int wy = threadIdx.y;
    const int nf = g_nf[b];
    const int nfpad = (nf + 127) & ~127;
    const int jb = blockIdx.x * 128;
    if (jb >= nfpad) return;
    const int j = jb + lane * 4;
    const float* base = g_costp + ((size_t)b * QQ) * TT;

    __shared__ float su[256];
    su[wy * 32 + lane] = g_u[b * QQ + z * 256 + wy * 32 + lane] * INV_EPS;
    __syncthreads();

    float m[4] = {BIGNEG, BIGNEG, BIGNEG, BIGNEG};
    float s[4] = {0.0f, 0.0f, 0.0f, 0.0f};

    for (int q0 = wy * 8; q0 < 256; q0 += 64) {
        float4 c[8];
        float uu[8];
#pragma unroll
        for (int r = 0; r < 8; r++) {
            c[r] = *(const float4*)(base + (size_t)(z * 256 + q0 + r) * TT + j);
            uu[r] = su[q0 + r];
        }
#pragma unroll
        for (int e = 0; e < 4; e++) {
            float a[8];
#pragma unroll
            for (int r = 0; r < 8; r++) {
                float ce = (e == 0) ? c[r].x : (e == 1) ? c[r].y : (e == 2) ? c[r].z : c[r].w;
                a[r] = fmaf(-INV_EPS, ce, uu[r]);
            }
            float mc = a[0];
#pragma unroll
            for (int r = 1; r < 8; r++) mc = fmaxf(mc, a[r]);
            mc = fmaxf(mc, BIGNEG);
            float sc = 0.0f;
#pragma unroll
            for (int r = 0; r < 8; r++) sc += __expf(a[r] - mc);
            lse_merge(m[e], s[e], mc, sc);
        }
    }

    __shared__ float sm[8][128];
    __shared__ float ss[8][128];
#pragma unroll
    for (int e = 0; e < 4; e++) {
        sm[wy][lane * 4 + e] = m[e];
        ss[wy][lane * 4 + e] = s[e];
    }
    __syncthreads();
    if (wy < 4) {  // 4 warps write 128 cols (one col per thread)
        int jj = jb + wy * 32 + lane;
        int li = wy * 32 + lane;
        float M = sm[0][li], S = ss[0][li];
#pragma unroll
        for (int w = 1; w < 8; w++) lse_merge(M, S, sm[w][li], ss[w][li]);
        size_t po = ((size_t)(b * 4 + z)) * TT + jj;
        g_vpm[po] = M;
        g_vps[po] = S;
    }
}

// ---------------- v merge: combine 4 split-K partials ----------------
__global__ void v_merge() {
    const int b = blockIdx.y;
    const int jj = blockIdx.x * 256 + threadIdx.x;
    if (jj >= g_nf[b]) return;
    float M = BIGNEG, S = 0.0f;
#pragma unroll
    for (int z = 0; z < 4; z++) {
        size_t po = ((size_t)(b * 4 + z)) * TT + jj;
        lse_merge(M, S, g_vpm[po], g_vps[po]);
    }
    g_vp[b * TT + jj] = -EPS * (__logf(S) + M);
}

// ---------------- final: unpack P row + argmax (first max) ----------------
__global__ void p_argmax_kernel(float* __restrict__ outP,
                                float* __restrict__ outIdx) {
    const int row = blockIdx.x;
    const int b = row >> 10;
    const int tid = threadIdx.x;
    const float* crow = g_costp + (size_t)row * TT;
    const float* vp = g_vp + b * TT;
    const int* cidx = g_colidx + b * TT;
    const int nf = g_nf[b];
    const int nfilt = g_nfilt[b];
    const int f0 = g_f0[b];
    const float fc = 2.0f * __uint_as_float(g_maxbits);
    const float vf = g_vf[b];
    const float u = g_u[row];
    const float pconst = __expf((u + vf - fc) * INV_EPS);

    __shared__ float rowbuf[1024];
    __shared__ float sv[256];
    __shared__ int si[256];

#pragma unroll
    for (int i = 0; i < 4; i++) rowbuf[tid + i * 256] = pconst;
    __syncthreads();

    float best = BIGNEG;
    int bidx = 0x7fffffff;
#pragma unroll
    for (int i = 0; i < 4; i++) {
        int j = tid + i * 256;
        if (j < nf) {
            float p = __expf((u + vp[j] - crow[j]) * INV_EPS);
            int t = cidx[j];
            rowbuf[t] = p;
            if (p > best || (p == best && t < bidx)) { best = p; bidx = t; }
        }
    }
    sv[tid] = best;
    si[tid] = bidx;
    __syncthreads();
#pragma unroll
    for (int st = 128; st > 0; st >>= 1) {
        if (tid < st) {
            float v2 = sv[tid + st];
            int i2 = si[tid + st];
            if (v2 > sv[tid] || (v2 == sv[tid] && i2 < si[tid])) {
                sv[tid] = v2;
                si[tid] = i2;
            }
        }
        __syncthreads();
    }

    if (outP) {
#pragma unroll
        for (int i = 0; i < 2; i++) {
            int j4 = (tid + i * 256) * 2;
            float2 o = make_float2(rowbuf[j4], rowbuf[j4 + 1]);
            *(float2*)(outP + (size_t)row * TT + j4) = o;
        }
    }
    if (tid == 0 && outIdx) {
        float bv = sv[0];
        int bi = si[0];
        if (nfilt > 0) {
            if (pconst > bv || (pconst == bv && f0 < bi)) { bv = pconst; bi = f0; }
        }
        outIdx[row] = (float)bi;
    }
}

// ---------------- launch ----------------
extern "C" void kernel_launch(void* const* d_in, const int* in_sizes, int n_in,
                              void* d_out, int out_size) {
    const float* preds = (const float*)d_in[0];
    const float* tgts = (const float*)d_in[1];
    const float* filt = (const float*)d_in[2];
    float* out = (float*)d_out;

    const int NP = BB * QQ * TT;
    const int NI = BB * QQ;
    float* outIdx = nullptr;
    float* outP = nullptr;
    if (out_size == NP + NI) { outIdx = out; outP = out + NI; }
    else if (out_size == NP) { outP = out; }
    else if (out_size == NI) { outIdx = out; }
    else { outIdx = out; outP = out + NI; }

    cudaFuncSetAttribute(cost_mma_kernel,
                         cudaFuncAttributeMaxDynamicSharedMemorySize, SM_TOTAL);

    init_kernel<<<(BB * TT + 255) / 256, 256>>>();
    scan_kernel<<<BB, 1024>>>(filt);
    {
        const int nwarps = 2 * BB * QQ;
        split_norms_kernel<<<(nwarps * 32 + 255) / 256, 256>>>(preds, tgts);
    }
    cost_mma_kernel<<<dim3(TT / 128, QQ / 128, BB), 256, SM_TOTAL>>>(filt);
    for (int it = 0; it < N_ITERS; it++) {
        u_update_p<<<BB * QQ / 8, 256>>>();
        vf_kernel<<<BB, 256>>>();
        v_partial<<<dim3(TT / 128, BB, 4), dim3(32, 8)>>>();
        v_merge<<<dim3(TT / 256, BB), 256>>>();
    }
    p_argmax_kernel<<<BB * QQ, 256>>>(outP, outIdx);
}

// round 7
// speedup vs baseline: 1.9114x; 1.0775x over previous
#include <cuda_runtime.h>
#include <cuda_bf16.h>
#include <math.h>
#include <stdint.h>

#define BB 16
#define QQ 1024
#define TT 1024
#define DD 256
#define EPS 0.1f
#define INV_EPS 10.0f
#define N_ITERS 5
#define BIGNEG (-1e30f)

#define K3 768
#define KC 64
#define STAGES 12
#define VZ 8              // v split-K factor

// ---------------- device scratch ----------------
__device__ float g_costp[(size_t)BB * QQ * TT];   // packed cost (unfiltered cols)
__device__ __nv_bfloat16 g_A3[(size_t)BB * QQ * K3];
__device__ __nv_bfloat16 g_B3[(size_t)BB * TT * K3];
__device__ float g_u[BB * QQ];
__device__ float g_vp[BB * TT];
__device__ float g_vf[BB];
__device__ float g_vpm[BB * VZ * TT];
__device__ float g_vps[BB * VZ * TT];
__device__ float g_x2[BB * QQ];
__device__ float g_y2[BB * TT];
__device__ int g_pref[BB * TT];
__device__ int g_colidx[BB * TT];
__device__ int g_nf[BB];
__device__ int g_nfilt[BB];
__device__ int g_f0[BB];
__device__ unsigned int g_maxbits;

// ---------------- PTX helpers (baseline sm_80+) ----------------
__device__ __forceinline__ uint32_t smem_to_u32(const void* p) {
    uint32_t a;
    asm("{ .reg .u64 t; cvta.to.shared.u64 t, %1; cvt.u32.u64 %0, t; }"
        : "=r"(a) : "l"(p));
    return a;
}
#define CP_ASYNC16(dst, src) \
    asm volatile("cp.async.cg.shared.global [%0], [%1], 16;" :: "r"(dst), "l"(src))
#define CP_COMMIT() asm volatile("cp.async.commit_group;")
#define CP_WAIT1() asm volatile("cp.async.wait_group 1;")
#define CP_WAIT0() asm volatile("cp.async.wait_group 0;")

__device__ __forceinline__ void ldsm_x4(uint32_t& r0, uint32_t& r1, uint32_t& r2,
                                        uint32_t& r3, uint32_t addr) {
    asm volatile("ldmatrix.sync.aligned.m8n8.x4.shared.b16 {%0,%1,%2,%3}, [%4];"
                 : "=r"(r0), "=r"(r1), "=r"(r2), "=r"(r3) : "r"(addr));
}
__device__ __forceinline__ void mma16816(float* d, const uint32_t* a, const uint32_t* b) {
    asm volatile(
        "mma.sync.aligned.m16n8k16.row.col.f32.bf16.bf16.f32 "
        "{%0,%1,%2,%3}, {%4,%5,%6,%7}, {%8,%9}, {%0,%1,%2,%3};"
        : "+f"(d[0]), "+f"(d[1]), "+f"(d[2]), "+f"(d[3])
        : "r"(a[0]), "r"(a[1]), "r"(a[2]), "r"(a[3]), "r"(b[0]), "r"(b[1]));
}
__device__ __forceinline__ void lse_merge(float& m, float& s, float mc, float sc) {
    float M = fmaxf(m, mc);
    s = s * __expf(m - M) + sc * __expf(mc - M);
    m = M;
}

// ---------------- init ----------------
__global__ void init_kernel() {
    int i = blockIdx.x * blockDim.x + threadIdx.x;
    if (i == 0) g_maxbits = 0u;
    if (i < BB) g_vf[i] = 0.0f;
    if (i < BB * TT) g_vp[i] = 0.0f;
}

// ---------------- scan: per-batch column metadata ----------------
__global__ void scan_kernel(const float* __restrict__ filt) {
    const int b = blockIdx.x;
    const int t = threadIdx.x;
    __shared__ int sh[1024];
    __shared__ int f0s;
    int flag = (filt[b * TT + t] <= 0.0f) ? 0 : 1;
    sh[t] = flag;
    if (t == 0) f0s = TT;
    __syncthreads();
    for (int o = 1; o < 1024; o <<= 1) {
        int add = (t >= o) ? sh[t - o] : 0;
        __syncthreads();
        sh[t] += add;
        __syncthreads();
    }
    int incl = sh[t];
    int excl = incl - flag;
    g_pref[b * TT + t] = excl;
    if (flag) g_colidx[b * TT + excl] = t;
    if (!flag) atomicMin(&f0s, t);
    __syncthreads();
    if (t == 1023) {
        g_nf[b] = incl;
        g_nfilt[b] = TT - incl;
    }
    if (t == 0) g_f0[b] = f0s;
}

// ------- split fp32 -> bf16 hi/lo (3-pass) + row norms; warp/row -----
__global__ void split_norms_kernel(const float* __restrict__ preds,
                                   const float* __restrict__ tgts) {
    int gw = (blockIdx.x * blockDim.x + threadIdx.x) >> 5;
    int lane = threadIdx.x & 31;
    if (gw >= 2 * BB * QQ) return;
    bool isA = gw < BB * QQ;
    int r = isA ? gw : gw - BB * QQ;
    const float* src = (isA ? preds : tgts) + (size_t)r * DD;
    __nv_bfloat16* dst = (isA ? g_A3 : g_B3) + (size_t)r * K3;

    float s = 0.0f;
#pragma unroll
    for (int i = 0; i < 2; i++) {
        int k = lane * 8 + i * 4;
        float4 x = *(const float4*)(src + k);
        s = fmaf(x.x, x.x, s);
        s = fmaf(x.y, x.y, s);
        s = fmaf(x.z, x.z, s);
        s = fmaf(x.w, x.w, s);
        __nv_bfloat16 hx = __float2bfloat16_rn(x.x);
        __nv_bfloat16 hy = __float2bfloat16_rn(x.y);
        __nv_bfloat16 hz = __float2bfloat16_rn(x.z);
        __nv_bfloat16 hw = __float2bfloat16_rn(x.w);
        __nv_bfloat16 lx = __float2bfloat16_rn(x.x - __bfloat162float(hx));
        __nv_bfloat16 ly = __float2bfloat16_rn(x.y - __bfloat162float(hy));
        __nv_bfloat16 lz = __float2bfloat16_rn(x.z - __bfloat162float(hz));
        __nv_bfloat16 lw = __float2bfloat16_rn(x.w - __bfloat162float(hw));
        __nv_bfloat162 h01{hx, hy}, h23{hz, hw}, l01{lx, ly}, l23{lz, lw};
        *(__nv_bfloat162*)(dst + 0 * DD + k) = h01;
        *(__nv_bfloat162*)(dst + 0 * DD + k + 2) = h23;
        *(__nv_bfloat162*)(dst + 1 * DD + k) = isA ? l01 : h01;
        *(__nv_bfloat162*)(dst + 1 * DD + k + 2) = isA ? l23 : h23;
        *(__nv_bfloat162*)(dst + 2 * DD + k) = isA ? h01 : l01;
        *(__nv_bfloat162*)(dst + 2 * DD + k + 2) = isA ? h23 : l23;
    }
#pragma unroll
    for (int o = 16; o > 0; o >>= 1) s += __shfl_xor_sync(0xffffffffu, s, o);
    if (lane == 0) {
        if (isA) g_x2[r] = s;
        else g_y2[r] = s;
    }
}

// --------- cost GEMM + fused pack: CTA = 128x128 tile, 3-stage pipeline -----
// dyn smem: 3 x 32KB stage buffers (96KB). Epilogue reuses [0..67584) as
// float tile[128][132].
#define SM_TOTAL 98304
__global__ void __launch_bounds__(256)
cost_mma_kernel(const float* __restrict__ filt) {
    extern __shared__ char smem[];
    const uint32_t sb = smem_to_u32(smem);
    const int b = blockIdx.z;
    const int m_base = blockIdx.y * 128;
    const int n_base = blockIdx.x * 128;
    const int tid = threadIdx.x;
    const int wid = tid >> 5;
    const int lane = tid & 31;
    const int warp_m = wid >> 2;
    const int warp_n = wid & 3;

    __shared__ int s_keptloc[128];
    __shared__ int s_cnt;
    __shared__ int s_pbase;
    __shared__ unsigned int smax;

    if (tid == 0) {
        int pb = g_pref[b * TT + n_base];
        s_pbase = pb;
        int pend = (n_base + 128 < TT) ? g_pref[b * TT + n_base + 128] : g_nf[b];
        s_cnt = pend - pb;
        smax = 0u;
    }

    const __nv_bfloat16* Ag = g_A3 + (size_t)(b * QQ + m_base) * K3;
    const __nv_bfloat16* Bg = g_B3 + (size_t)(b * TT + n_base) * K3;

    auto load_stage = [&](int s, int buf) {
        uint32_t abase = sb + (uint32_t)buf * 32768u;
        uint32_t bbase = abase + 16384u;
#pragma unroll
        for (int v = 0; v < 4; v++) {
            int idx = tid + v * 256;
            int r = idx >> 3;
            int g = idx & 7;
            uint32_t off = (uint32_t)(r * 128 + ((g ^ (r & 7)) << 4));
            CP_ASYNC16(abase + off, Ag + (size_t)r * K3 + s * KC + g * 8);
            CP_ASYNC16(bbase + off, Bg + (size_t)r * K3 + s * KC + g * 8);
        }
    };

    const int laneA_r = (lane & 7) + ((lane >> 3) & 1) * 8;
    const int khA = (lane >> 4) & 1;
    const int laneB_r = (lane & 7) + ((lane >> 4) & 1) * 8;
    const int khB = (lane >> 3) & 1;
    const int xorA = laneA_r & 7;
    const int xorB = laneB_r & 7;

    float acc[4][4][4];
#pragma unroll
    for (int i = 0; i < 4; i++)
#pragma unroll
        for (int j = 0; j < 4; j++)
#pragma unroll
            for (int e = 0; e < 4; e++) acc[i][j][e] = 0.0f;

    load_stage(0, 0);
    CP_COMMIT();
    load_stage(1, 1);
    CP_COMMIT();

    for (int s = 0; s < STAGES; s++) {
        if (s + 1 < STAGES) { CP_WAIT1(); }   // stage s complete
        else               { CP_WAIT0(); }
        __syncthreads();                       // buffer (s-1)%3 now free everywhere
        if (s + 2 < STAGES) {
            load_stage(s + 2, (s + 2) % 3);
            CP_COMMIT();
        }

        uint32_t abase = sb + (uint32_t)(s % 3) * 32768u;
        uint32_t bbase = abase + 16384u;
#pragma unroll
        for (int kq = 0; kq < 4; kq++) {
            uint32_t afrag[4][4];
            uint32_t bfrag[4][2];
#pragma unroll
            for (int im = 0; im < 4; im++) {
                int row = warp_m * 64 + im * 16 + laneA_r;
                uint32_t addr = abase + (uint32_t)(row * 128 + (((khA + 2 * kq) ^ xorA) << 4));
                ldsm_x4(afrag[im][0], afrag[im][1], afrag[im][2], afrag[im][3], addr);
            }
#pragma unroll
            for (int ip = 0; ip < 2; ip++) {
                int row = warp_n * 32 + ip * 16 + laneB_r;
                uint32_t addr = bbase + (uint32_t)(row * 128 + (((khB + 2 * kq) ^ xorB) << 4));
                ldsm_x4(bfrag[ip * 2][0], bfrag[ip * 2][1],
                        bfrag[ip * 2 + 1][0], bfrag[ip * 2 + 1][1], addr);
            }
#pragma unroll
            for (int im = 0; im < 4; im++)
#pragma unroll
                for (int in = 0; in < 4; in++)
                    mma16816(acc[im][in], afrag[im], bfrag[in]);
        }
    }
    __syncthreads();

    // ----- fused epilogue -----
    if (tid < 128) {
        int t = n_base + tid;
        bool kept = filt[b * TT + t] > 0.0f;
        int p = g_pref[b * TT + t];
        if (kept) s_keptloc[p - s_pbase] = tid;
    }

    const float* x2p = g_x2 + b * QQ + m_base;
    const float* y2p = g_y2 + b * TT + n_base;
    float* tile = (float*)smem;    // [128][132]
    float tmax = 0.0f;
#pragma unroll
    for (int im = 0; im < 4; im++) {
        int m0 = warp_m * 64 + im * 16 + (lane >> 2);
        float xi0 = x2p[m0];
        float xi1 = x2p[m0 + 8];
#pragma unroll
        for (int in = 0; in < 4; in++) {
            int n0 = warp_n * 32 + in * 8 + (lane & 3) * 2;
            float y0 = y2p[n0];
            float y1 = y2p[n0 + 1];
            float c00 = sqrtf(fmaxf(fmaf(-2.0f, acc[im][in][0], xi0 + y0), 0.0f));
            float c01 = sqrtf(fmaxf(fmaf(-2.0f, acc[im][in][1], xi0 + y1), 0.0f));
            float c10 = sqrtf(fmaxf(fmaf(-2.0f, acc[im][in][2], xi1 + y0), 0.0f));
            float c11 = sqrtf(fmaxf(fmaf(-2.0f, acc[im][in][3], xi1 + y1), 0.0f));
            tmax = fmaxf(tmax, fmaxf(fmaxf(c00, c01), fmaxf(c10, c11)));
            tile[m0 * 132 + n0] = c00;
            tile[m0 * 132 + n0 + 1] = c01;
            tile[(m0 + 8) * 132 + n0] = c10;
            tile[(m0 + 8) * 132 + n0 + 1] = c11;
        }
    }
    __syncthreads();

    {
        const int kept = s_cnt;
        const int pbase = s_pbase;
        for (int r = wid; r < 128; r += 8) {
            size_t dst = ((size_t)(b * QQ + m_base + r)) * TT + pbase;
            for (int j = lane; j < kept; j += 32)
                g_costp[dst + j] = tile[r * 132 + s_keptloc[j]];
        }
    }
    if (blockIdx.x == 0) {
        const int nf = g_nf[b];
        const int nfpad = (nf + 127) & ~127;
        const float INF = __int_as_float(0x7f800000);
        for (int r = wid; r < 128; r += 8) {
            size_t dst = ((size_t)(b * QQ + m_base + r)) * TT;
            for (int j = nf + lane; j < nfpad; j += 32) g_costp[dst + j] = INF;
        }
    }

#pragma unroll
    for (int o = 16; o > 0; o >>= 1)
        tmax = fmaxf(tmax, __shfl_xor_sync(0xffffffffu, tmax, o));
    if (lane == 0) atomicMax(&smax, __float_as_uint(tmax));
    __syncthreads();
    if (tid == 0) atomicMax(&g_maxbits, smax);
}

// ---------------- u update: 8 rows per block, vp cached in smem -------------
__global__ void u_update_p() {
    const int row0 = blockIdx.x * 8;
    const int b = row0 >> 10;
    const int tid = threadIdx.x;
    const int w = tid >> 5;
    const int lane = tid & 31;
    const int nf = g_nf[b];
    const int nfpad = (nf + 127) & ~127;
    const int nk = nfpad >> 7;
    const float fc = 2.0f * __uint_as_float(g_maxbits);
    const float vf = g_vf[b];
    const float nfl = (float)g_nfilt[b];

    __shared__ float svp[1024];
    for (int j = tid; j < nfpad; j += 256) svp[j] = g_vp[b * TT + j] * INV_EPS;
    __syncthreads();

    const int row = row0 + w;
    const float* crow = g_costp + (size_t)row * TT;

    float m = BIGNEG, s = 0.0f;
    int k = 0;
    for (; k + 1 < nk; k += 2) {
        int j0 = k * 128 + lane * 4;
        int j1 = j0 + 128;
        float4 c0 = *(const float4*)(crow + j0);
        float4 c1 = *(const float4*)(crow + j1);
        float4 v0 = *(const float4*)(svp + j0);
        float4 v1 = *(const float4*)(svp + j1);
        float a0 = fmaf(-INV_EPS, c0.x, v0.x), a1 = fmaf(-INV_EPS, c0.y, v0.y);
        float a2 = fmaf(-INV_EPS, c0.z, v0.z), a3 = fmaf(-INV_EPS, c0.w, v0.w);
        float b0 = fmaf(-INV_EPS, c1.x, v1.x), b1 = fmaf(-INV_EPS, c1.y, v1.y);
        float b2 = fmaf(-INV_EPS, c1.z, v1.z), b3 = fmaf(-INV_EPS, c1.w, v1.w);
        float mc = fmaxf(fmaxf(fmaxf(a0, a1), fmaxf(a2, a3)),
                         fmaxf(fmaxf(b0, b1), fmaxf(b2, b3)));
        mc = fmaxf(mc, BIGNEG);
        float sc = __expf(a0 - mc) + __expf(a1 - mc) + __expf(a2 - mc) + __expf(a3 - mc) +
                   __expf(b0 - mc) + __expf(b1 - mc) + __expf(b2 - mc) + __expf(b3 - mc);
        lse_merge(m, s, mc, sc);
    }
    if (k < nk) {
        int j0 = k * 128 + lane * 4;
        float4 c0 = *(const float4*)(crow + j0);
        float4 v0 = *(const float4*)(svp + j0);
        float a0 = fmaf(-INV_EPS, c0.x, v0.x), a1 = fmaf(-INV_EPS, c0.y, v0.y);
        float a2 = fmaf(-INV_EPS, c0.z, v0.z), a3 = fmaf(-INV_EPS, c0.w, v0.w);
        float mc = fmaxf(fmaxf(fmaxf(a0, a1), fmaxf(a2, a3)), BIGNEG);
        float sc = __expf(a0 - mc) + __expf(a1 - mc) + __expf(a2 - mc) + __expf(a3 - mc);
        lse_merge(m, s, mc, sc);
    }
#pragma unroll
    for (int o = 16; o > 0; o >>= 1) {
        float m2 = __shfl_xor_sync(0xffffffffu, m, o);
        float s2 = __shfl_xor_sync(0xffffffffu, s, o);
        lse_merge(m, s, m2, s2);
    }
    lse_merge(m, s, (vf - fc) * INV_EPS, nfl);
    if (lane == 0) g_u[row] = -EPS * (__logf(s) + m);
}

// ---------------- v partial: grid (8, BB, VZ), block (32,8); 128 q each -----
__global__ void v_partial() {
    const int b = blockIdx.y;
    const int z = blockIdx.z;
    const int lane = threadIdx.x;
    const int wy = threadIdx.y;
    const int nfpad = (g_nf[b] + 127) & ~127;
    const int jb = blockIdx.x * 128;
    if (jb >= nfpad) return;
    const int j = jb + lane * 4;
    const float* base = g_costp + ((size_t)b * QQ) * TT;

    __shared__ float su[128];
    if (threadIdx.y < 4) {
        int q = threadIdx.y * 32 + lane;
        su[q] = g_u[b * QQ + z * 128 + q] * INV_EPS;
    }
    __syncthreads();

    float m[4] = {BIGNEG, BIGNEG, BIGNEG, BIGNEG};
    float s[4] = {0.0f, 0.0f, 0.0f, 0.0f};

    for (int q0 = wy * 8; q0 < 128; q0 += 64) {
        float4 c[8];
        float uu[8];
#pragma unroll
        for (int r = 0; r < 8; r++) {
            c[r] = *(const float4*)(base + (size_t)(z * 128 + q0 + r) * TT + j);
            uu[r] = su[q0 + r];
        }
#pragma unroll
        for (int e = 0; e < 4; e++) {
            float a[8];
#pragma unroll
            for (int r = 0; r < 8; r++) {
                float ce = (e == 0) ? c[r].x : (e == 1) ? c[r].y : (e == 2) ? c[r].z : c[r].w;
                a[r] = fmaf(-INV_EPS, ce, uu[r]);
            }
            float mc = a[0];
#pragma unroll
            for (int r = 1; r < 8; r++) mc = fmaxf(mc, a[r]);
            mc = fmaxf(mc, BIGNEG);
            float sc = 0.0f;
#pragma unroll
            for (int r = 0; r < 8; r++) sc += __expf(a[r] - mc);
            lse_merge(m[e], s[e], mc, sc);
        }
    }

    __shared__ float sm[8][128];
    __shared__ float ss[8][128];
#pragma unroll
    for (int e = 0; e < 4; e++) {
        sm[wy][lane * 4 + e] = m[e];
        ss[wy][lane * 4 + e] = s[e];
    }
    __syncthreads();
    if (wy < 4) {
        int li = wy * 32 + lane;
        float M = sm[0][li], S = ss[0][li];
#pragma unroll
        for (int w = 1; w < 8; w++) lse_merge(M, S, sm[w][li], ss[w][li]);
        size_t po = ((size_t)(b * VZ + z)) * TT + jb + li;
        g_vpm[po] = M;
        g_vps[po] = S;
    }
}

// ------- v merge (+ vf for block x==0): combine VZ split-K partials --------
__global__ void v_merge_vf() {
    const int b = blockIdx.y;
    const int tid = threadIdx.x;
    const int jj = blockIdx.x * 256 + tid;
    if (jj < g_nf[b]) {
        float M = BIGNEG, S = 0.0f;
#pragma unroll
        for (int z = 0; z < VZ; z++) {
            size_t po = ((size_t)(b * VZ + z)) * TT + jj;
            lse_merge(M, S, g_vpm[po], g_vps[po]);
        }
        g_vp[b * TT + jj] = -EPS * (__logf(S) + M);
    }
    if (blockIdx.x == 0) {
        // vf[b] = fc - eps*LSE_q(u*10)
        const float* ub = g_u + b * QQ;
        __shared__ float sh8[8];
        float4 u4 = *(const float4*)(ub + tid * 4);
        float a0 = u4.x * INV_EPS, a1 = u4.y * INV_EPS;
        float a2 = u4.z * INV_EPS, a3 = u4.w * INV_EPS;
        float m = fmaxf(fmaxf(a0, a1), fmaxf(a2, a3));
#pragma unroll
        for (int o = 16; o > 0; o >>= 1) m = fmaxf(m, __shfl_xor_sync(0xffffffffu, m, o));
        int w = tid >> 5;
        if ((tid & 31) == 0) sh8[w] = m;
        __syncthreads();
        float M = sh8[0];
#pragma unroll
        for (int i = 1; i < 8; i++) M = fmaxf(M, sh8[i]);
        __syncthreads();
        float s = __expf(a0 - M) + __expf(a1 - M) + __expf(a2 - M) + __expf(a3 - M);
#pragma unroll
        for (int o = 16; o > 0; o >>= 1) s += __shfl_xor_sync(0xffffffffu, s, o);
        if ((tid & 31) == 0) sh8[w] = s;
        __syncthreads();
        if (tid == 0) {
            float S = sh8[0];
#pragma unroll
            for (int i = 1; i < 8; i++) S += sh8[i];
            const float fc = 2.0f * __uint_as_float(g_maxbits);
            g_vf[b] = -EPS * (__logf(S) + M) + fc;
        }
    }
}

// ---------------- final: unpack P row + argmax (first max) ----------------
__global__ void p_argmax_kernel(float* __restrict__ outP,
                                float* __restrict__ outIdx) {
    const int row = blockIdx.x;
    const int b = row >> 10;
    const int tid = threadIdx.x;
    const float* crow = g_costp + (size_t)row * TT;
    const float* vp = g_vp + b * TT;
    const int* cidx = g_colidx + b * TT;
    const int nf = g_nf[b];
    const int nfilt = g_nfilt[b];
    const int f0 = g_f0[b];
    const float fc = 2.0f * __uint_as_float(g_maxbits);
    const float vf = g_vf[b];
    const float u = g_u[row];
    const float pconst = __expf((u + vf - fc) * INV_EPS);

    __shared__ float rowbuf[1024];
    __shared__ float sv[256];
    __shared__ int si[256];

#pragma unroll
    for (int i = 0; i < 4; i++) rowbuf[tid + i * 256] = pconst;
    __syncthreads();

    float best = BIGNEG;
    int bidx = 0x7fffffff;
#pragma unroll
    for (int i = 0; i < 4; i++) {
        int j = tid + i * 256;
        if (j < nf) {
            float p = __expf((u + vp[j] - crow[j]) * INV_EPS);
            int t = cidx[j];
            rowbuf[t] = p;
            if (p > best || (p == best && t < bidx)) { best = p; bidx = t; }
        }
    }
    sv[tid] = best;
    si[tid] = bidx;
    __syncthreads();
#pragma unroll
    for (int st = 128; st > 0; st >>= 1) {
        if (tid < st) {
            float v2 = sv[tid + st];
            int i2 = si[tid + st];
            if (v2 > sv[tid] || (v2 == sv[tid] && i2 < si[tid])) {
                sv[tid] = v2;
                si[tid] = i2;
            }
        }
        __syncthreads();
    }

    if (outP) {
#pragma unroll
        for (int i = 0; i < 2; i++) {
            int j4 = (tid + i * 256) * 2;
            float2 o = make_float2(rowbuf[j4], rowbuf[j4 + 1]);
            *(float2*)(outP + (size_t)row * TT + j4) = o;
        }
    }
    if (tid == 0 && outIdx) {
        float bv = sv[0];
        int bi = si[0];
        if (nfilt > 0) {
            if (pconst > bv || (pconst == bv && f0 < bi)) { bv = pconst; bi = f0; }
        }
        outIdx[row] = (float)bi;
    }
}

// ---------------- launch ----------------
extern "C" void kernel_launch(void* const* d_in, const int* in_sizes, int n_in,
                              void* d_out, int out_size) {
    const float* preds = (const float*)d_in[0];
    const float* tgts = (const float*)d_in[1];
    const float* filt = (const float*)d_in[2];
    float* out = (float*)d_out;

    const int NP = BB * QQ * TT;
    const int NI = BB * QQ;
    float* outIdx = nullptr;
    float* outP = nullptr;
    if (out_size == NP + NI) { outIdx = out; outP = out + NI; }
    else if (out_size == NP) { outP = out; }
    else if (out_size == NI) { outIdx = out; }
    else { outIdx = out; outP = out + NI; }

    cudaFuncSetAttribute(cost_mma_kernel,
                         cudaFuncAttributeMaxDynamicSharedMemorySize, SM_TOTAL);

    init_kernel<<<(BB * TT + 255) / 256, 256>>>();
    scan_kernel<<<BB, 1024>>>(filt);
    {
        const int nwarps = 2 * BB * QQ;
        split_norms_kernel<<<(nwarps * 32 + 255) / 256, 256>>>(preds, tgts);
    }
    cost_mma_kernel<<<dim3(TT / 128, QQ / 128, BB), 256, SM_TOTAL>>>(filt);
    for (int it = 0; it < N_ITERS; it++) {
        u_update_p<<<BB * QQ / 8, 256>>>();
        v_partial<<<dim3(TT / 128, BB, VZ), dim3(32, 8)>>>();
        v_merge_vf<<<dim3(TT / 256, BB), 256>>>();
    }
    p_argmax_kernel<<<BB * QQ, 256>>>(outP, outIdx);
}